// round 2
// baseline (speedup 1.0000x reference)
#include <cuda_runtime.h>
#include <math.h>

#define Bn   2
#define Tn   2048
#define Cn   1024
#define Hn   16
#define HDn  64
#define HD2n 32
#define Mn   (Bn * Tn)          // 4096
#define N3n  (3 * Cn)           // 3072

// Scratch (allocation-free rule: __device__ globals)
__device__ float g_qkv[(size_t)Mn * N3n];   // 50 MB: [m][q|k|v]
__device__ float g_att[(size_t)Mn * Cn];    // 16 MB: attention output

// ---------------------------------------------------------------------------
// SGEMM with bias: C[M,N] = A[M,K] @ B[K,N] + bias[N]
// 128x128 tile, BK=8, 256 threads, 8x8 per-thread micro-tile.
// M,N,K all multiples of 128/8 here; no bounds checks.
// ---------------------------------------------------------------------------
__global__ __launch_bounds__(256) void sgemm_bias_kernel(
    int M, int N, int K,
    const float* __restrict__ A, const float* __restrict__ B,
    const float* __restrict__ bias, float* __restrict__ C)
{
    __shared__ float As[8][128];
    __shared__ float Bs[8][128];

    const int tid  = threadIdx.x;
    const int brow = blockIdx.y * 128;
    const int bcol = blockIdx.x * 128;

    const int aRow = tid >> 1;            // 0..127
    const int aCol = (tid & 1) * 4;       // 0 or 4
    const int bRow = tid >> 5;            // 0..7
    const int bCol = (tid & 31) * 4;      // 0..124

    const int tr = (tid >> 4) * 8;        // 0..120
    const int tc = (tid & 15) * 8;        // 0..120

    float acc[8][8];
    #pragma unroll
    for (int i = 0; i < 8; i++)
        #pragma unroll
        for (int j = 0; j < 8; j++) acc[i][j] = 0.f;

    const float* Ap = A + (size_t)(brow + aRow) * K + aCol;
    const float* Bp = B + (size_t)bRow * N + bcol + bCol;

    for (int k0 = 0; k0 < K; k0 += 8) {
        float4 a4 = *(const float4*)(Ap + k0);
        As[aCol + 0][aRow] = a4.x;
        As[aCol + 1][aRow] = a4.y;
        As[aCol + 2][aRow] = a4.z;
        As[aCol + 3][aRow] = a4.w;
        *(float4*)(&Bs[bRow][bCol]) = *(const float4*)(Bp + (size_t)k0 * N);
        __syncthreads();

        #pragma unroll
        for (int kk = 0; kk < 8; kk++) {
            float ar[8], br[8];
            *(float4*)(ar)     = *(const float4*)(&As[kk][tr]);
            *(float4*)(ar + 4) = *(const float4*)(&As[kk][tr + 4]);
            *(float4*)(br)     = *(const float4*)(&Bs[kk][tc]);
            *(float4*)(br + 4) = *(const float4*)(&Bs[kk][tc + 4]);
            #pragma unroll
            for (int i = 0; i < 8; i++)
                #pragma unroll
                for (int j = 0; j < 8; j++)
                    acc[i][j] += ar[i] * br[j];
        }
        __syncthreads();
    }

    #pragma unroll
    for (int i = 0; i < 8; i++) {
        float* crow = C + (size_t)(brow + tr + i) * N + bcol + tc;
        #pragma unroll
        for (int j = 0; j < 8; j += 4) {
            float4 o;
            o.x = acc[i][j + 0] + bias[bcol + tc + j + 0];
            o.y = acc[i][j + 1] + bias[bcol + tc + j + 1];
            o.z = acc[i][j + 2] + bias[bcol + tc + j + 2];
            o.w = acc[i][j + 3] + bias[bcol + tc + j + 3];
            *(float4*)(crow + j) = o;
        }
    }
}

// ---------------------------------------------------------------------------
// RoPE on q and k inside g_qkv. One thread per (m, h, d-pair, {q,k}).
// total = Mn * Hn * HD2n * 2 = 4,194,304 threads
// ---------------------------------------------------------------------------
__global__ __launch_bounds__(256) void rope_kernel(
    float* qkv, const float* __restrict__ fcos, const float* __restrict__ fsin)
{
    int idx = blockIdx.x * blockDim.x + threadIdx.x;
    int d     = idx & 31;
    int h     = (idx >> 5) & 15;
    int m     = (idx >> 9) & 4095;
    int which = idx >> 21;          // 0 = q, 1 = k
    int t     = m & (Tn - 1);

    float c = fcos[t * HD2n + d];
    float s = fsin[t * HD2n + d];
    float* p = qkv + (size_t)m * N3n + which * Cn + h * HDn + d;
    float u1 = p[0];
    float u2 = p[HD2n];
    p[0]    = u1 * c - u2 * s;
    p[HD2n] = u1 * s + u2 * c;
}

// ---------------------------------------------------------------------------
// Causal flash attention, fp32. BR=128 queries x BC=64 keys per tile.
// 128 threads: ty=tid/8 owns 8 query rows, tx=tid%8 owns 8 cols (keys for S,
// head-dims for O). Online softmax, P staged through smem (stride-65 pad).
// smem = (128 + 64 + 64 + 128) * 65 * 4 = 99840 B -> 2 CTAs/SM.
// ---------------------------------------------------------------------------
#define FA_SMEM (384 * 65 * 4)

__global__ __launch_bounds__(128) void flash_kernel(
    const float* __restrict__ qkv, float* __restrict__ out)
{
    extern __shared__ float sm[];
    float* Qs = sm;                 // [128][65]
    float* Ks = Qs + 128 * 65;      // [64][65]
    float* Vs = Ks + 64 * 65;       // [64][65]
    float* Ps = Vs + 64 * 65;       // [128][65]

    const int tid = threadIdx.x;
    const int ty  = tid >> 3;       // 0..15
    const int tx  = tid & 7;        // 0..7
    const int rbase = ty * 8;
    const int cb    = tx * 8;

    const int qb = 15 - blockIdx.x;      // heavy blocks first
    const int h  = blockIdx.y;
    const int b  = blockIdx.z;
    const size_t qrow0 = (size_t)b * Tn + qb * 128;
    const float scale = 0.125f;          // 1/sqrt(64)
    const float L2E = 1.44269504088896f;

    // load Q tile (pre-scaled)
    for (int i = tid; i < 128 * 16; i += 128) {
        int r = i >> 4, dg = (i & 15) * 4;
        float4 q4 = *(const float4*)(qkv + (qrow0 + r) * N3n + h * HDn + dg);
        float* dst = Qs + r * 65 + dg;
        dst[0] = q4.x * scale; dst[1] = q4.y * scale;
        dst[2] = q4.z * scale; dst[3] = q4.w * scale;
    }

    float m_i[8], l_i[8], o[8][8];
    #pragma unroll
    for (int i = 0; i < 8; i++) {
        m_i[i] = -1e30f; l_i[i] = 0.f;
        #pragma unroll
        for (int j = 0; j < 8; j++) o[i][j] = 0.f;
    }

    const int nkb = qb * 2 + 2;
    for (int kb = 0; kb < nkb; kb++) {
        __syncthreads();   // protect Q (first iter) / Ks,Vs,Ps reuse
        // load K, V tiles
        const size_t krow0 = (size_t)b * Tn + kb * 64;
        for (int i = tid; i < 64 * 16; i += 128) {
            int r = i >> 4, dg = (i & 15) * 4;
            const float* base = qkv + (krow0 + r) * N3n + Cn + h * HDn + dg;
            float4 k4 = *(const float4*)base;
            float4 v4 = *(const float4*)(base + Cn);
            float* kd = Ks + r * 65 + dg;
            kd[0] = k4.x; kd[1] = k4.y; kd[2] = k4.z; kd[3] = k4.w;
            float* vd = Vs + r * 65 + dg;
            vd[0] = v4.x; vd[1] = v4.y; vd[2] = v4.z; vd[3] = v4.w;
        }
        __syncthreads();

        // S = (Q*scale) K^T
        float s[8][8];
        #pragma unroll
        for (int i = 0; i < 8; i++)
            #pragma unroll
            for (int j = 0; j < 8; j++) s[i][j] = 0.f;

        #pragma unroll 8
        for (int d = 0; d < 64; d++) {
            float ar[8], br[8];
            #pragma unroll
            for (int i = 0; i < 8; i++) ar[i] = Qs[(rbase + i) * 65 + d];
            #pragma unroll
            for (int j = 0; j < 8; j++) br[j] = Ks[(cb + j) * 65 + d];
            #pragma unroll
            for (int i = 0; i < 8; i++)
                #pragma unroll
                for (int j = 0; j < 8; j++)
                    s[i][j] += ar[i] * br[j];
        }

        // causal mask (only the last two key blocks can cross the diagonal)
        if (kb >= 2 * qb) {
            #pragma unroll
            for (int i = 0; i < 8; i++)
                #pragma unroll
                for (int j = 0; j < 8; j++)
                    if (kb * 64 + cb + j > qb * 128 + rbase + i)
                        s[i][j] = -1e30f;
        }

        // online softmax per row (reduce across 8 tx lanes)
        #pragma unroll
        for (int i = 0; i < 8; i++) {
            float mx = s[i][0];
            #pragma unroll
            for (int j = 1; j < 8; j++) mx = fmaxf(mx, s[i][j]);
            mx = fmaxf(mx, __shfl_xor_sync(0xffffffffu, mx, 1));
            mx = fmaxf(mx, __shfl_xor_sync(0xffffffffu, mx, 2));
            mx = fmaxf(mx, __shfl_xor_sync(0xffffffffu, mx, 4));
            float mnew  = fmaxf(m_i[i], mx);
            float alpha = exp2f((m_i[i] - mnew) * L2E);
            m_i[i] = mnew;
            float rs = 0.f;
            #pragma unroll
            for (int j = 0; j < 8; j++) {
                float p = exp2f((s[i][j] - mnew) * L2E);
                s[i][j] = p;
                rs += p;
            }
            rs += __shfl_xor_sync(0xffffffffu, rs, 1);
            rs += __shfl_xor_sync(0xffffffffu, rs, 2);
            rs += __shfl_xor_sync(0xffffffffu, rs, 4);
            l_i[i] = l_i[i] * alpha + rs;
            #pragma unroll
            for (int j = 0; j < 8; j++) o[i][j] *= alpha;
            #pragma unroll
            for (int j = 0; j < 8; j++)
                Ps[(rbase + i) * 65 + cb + j] = s[i][j];
        }
        __syncthreads();

        // O += P @ V
        #pragma unroll 4
        for (int c = 0; c < 64; c++) {
            float pr[8], vr[8];
            #pragma unroll
            for (int i = 0; i < 8; i++) pr[i] = Ps[(rbase + i) * 65 + c];
            #pragma unroll
            for (int j = 0; j < 8; j++) vr[j] = Vs[c * 65 + cb + j];
            #pragma unroll
            for (int i = 0; i < 8; i++)
                #pragma unroll
                for (int j = 0; j < 8; j++)
                    o[i][j] += pr[i] * vr[j];
        }
    }

    // epilogue: normalize and store
    #pragma unroll
    for (int i = 0; i < 8; i++) {
        float inv = 1.0f / l_i[i];
        float* dst = out + (qrow0 + rbase + i) * Cn + h * HDn + cb;
        float4 o0, o1;
        o0.x = o[i][0] * inv; o0.y = o[i][1] * inv;
        o0.z = o[i][2] * inv; o0.w = o[i][3] * inv;
        o1.x = o[i][4] * inv; o1.y = o[i][5] * inv;
        o1.z = o[i][6] * inv; o1.w = o[i][7] * inv;
        *(float4*)dst       = o0;
        *(float4*)(dst + 4) = o1;
    }
}

// ---------------------------------------------------------------------------
extern "C" void kernel_launch(void* const* d_in, const int* in_sizes, int n_in,
                              void* d_out, int out_size)
{
    const float* x     = (const float*)d_in[0];
    const float* fcos  = (const float*)d_in[1];
    const float* fsin  = (const float*)d_in[2];
    const float* Wqkv  = (const float*)d_in[3];
    const float* bqkv  = (const float*)d_in[4];
    const float* Wproj = (const float*)d_in[5];
    const float* bproj = (const float*)d_in[6];
    float* out = (float*)d_out;

    float* qkv = nullptr;
    float* att = nullptr;
    cudaGetSymbolAddress((void**)&qkv, g_qkv);
    cudaGetSymbolAddress((void**)&att, g_att);

    cudaFuncSetAttribute(flash_kernel,
                         cudaFuncAttributeMaxDynamicSharedMemorySize, FA_SMEM);

    // 1) qkv = x @ Wqkv + bqkv     [4096 x 3072, K=1024]
    sgemm_bias_kernel<<<dim3(N3n / 128, Mn / 128), 256>>>(
        Mn, N3n, Cn, x, Wqkv, bqkv, qkv);

    // 2) RoPE on q, k in-place
    rope_kernel<<<(Mn * Hn * HD2n * 2) / 256, 256>>>(qkv, fcos, fsin);

    // 3) causal flash attention -> g_att
    flash_kernel<<<dim3(Tn / 128, Hn, Bn), 128, FA_SMEM>>>(qkv, att);

    // 4) out = att @ Wproj + bproj  [4096 x 1024, K=1024]
    sgemm_bias_kernel<<<dim3(Cn / 128, Mn / 128), 256>>>(
        Mn, Cn, Cn, att, Wproj, bproj, out);
}

// round 4
// speedup vs baseline: 1.4037x; 1.4037x over previous
#include <cuda_runtime.h>
#include <cuda_bf16.h>
#include <cstdint>
#include <math.h>

#define Bn   2
#define Tn   2048
#define Cn   1024
#define Hn   16
#define HDn  64
#define HD2n 32
#define Mn   (Bn * Tn)          // 4096
#define N3n  (3 * Cn)           // 3072
#define Kn   1024

// ---------------------------------------------------------------------------
// Scratch pool (allocation-free rule: __device__ global)
// ---------------------------------------------------------------------------
#define OFF_QKV   0ull                                   // fp32 [4096][3072]
#define OFF_ATT   (OFF_QKV   + 50331648ull)              // fp32 [4096][1024]
#define OFF_XH    (OFF_ATT   + 16777216ull)              // bf16 [4096][1024]
#define OFF_XL    (OFF_XH    + 8388608ull)
#define OFF_WQH   (OFF_XL    + 8388608ull)               // bf16 [3072][1024] (W^T)
#define OFF_WQL   (OFF_WQH   + 6291456ull)
#define OFF_WPH   (OFF_WQL   + 6291456ull)               // bf16 [1024][1024] (W^T)
#define OFF_WPL   (OFF_WPH   + 2097152ull)
#define OFF_AH    (OFF_WPL   + 2097152ull)               // bf16 [4096][1024]
#define OFF_AL    (OFF_AH    + 8388608ull)
#define POOL_SZ   (OFF_AL    + 8388608ull)

__device__ __align__(1024) unsigned char g_pool[POOL_SZ];

// ---------------------------------------------------------------------------
// mma.sync helper (sm_80-compatible PTX; lowers to HMMA on sm_103)
// D(16x8,f32) += A(16x16,bf16 row) * B(16x8,bf16 col)
// ---------------------------------------------------------------------------
#define MMA16816(d, a, b) \
    asm volatile( \
        "mma.sync.aligned.m16n8k16.row.col.f32.bf16.bf16.f32 " \
        "{%0,%1,%2,%3}, {%4,%5,%6,%7}, {%8,%9}, {%0,%1,%2,%3};" \
        : "+f"((d)[0]), "+f"((d)[1]), "+f"((d)[2]), "+f"((d)[3]) \
        : "r"((a)[0]), "r"((a)[1]), "r"((a)[2]), "r"((a)[3]), \
          "r"((b)[0]), "r"((b)[1]))

#define CP_ASYNC16(dst, src) \
    asm volatile("cp.async.cg.shared.global [%0], [%1], 16;" \
                 :: "r"(dst), "l"(src) : "memory")
#define CP_COMMIT() asm volatile("cp.async.commit_group;" ::: "memory")

__device__ __forceinline__ uint32_t smem_u32(const void* p) {
    uint32_t a;
    asm("{ .reg .u64 t; cvta.to.shared.u64 t, %1; cvt.u32.u64 %0, t; }"
        : "=r"(a) : "l"(p));
    return a;
}

// ---------------------------------------------------------------------------
// Split fp32 -> bf16 hi/lo
// ---------------------------------------------------------------------------
__global__ __launch_bounds__(256) void split_kernel(
    const float* __restrict__ in, __nv_bfloat16* __restrict__ h,
    __nv_bfloat16* __restrict__ l, int n)
{
    int i = blockIdx.x * 256 + threadIdx.x;
    if (i < n) {
        float v = in[i];
        __nv_bfloat16 hv = __float2bfloat16(v);
        h[i] = hv;
        l[i] = __float2bfloat16(v - __bfloat162float(hv));
    }
}

// ---------------------------------------------------------------------------
// Transpose + split: W[K][N] fp32 -> Th, Tl [N][K] bf16
// ---------------------------------------------------------------------------
__global__ __launch_bounds__(256) void transpose_split_kernel(
    const float* __restrict__ W, __nv_bfloat16* __restrict__ Th,
    __nv_bfloat16* __restrict__ Tl, int K, int N)
{
    __shared__ float t[32][33];
    int n0 = blockIdx.x * 32, k0 = blockIdx.y * 32;
    int tx = threadIdx.x & 31, ty = threadIdx.x >> 5;   // 32 x 8
    #pragma unroll
    for (int r = 0; r < 4; r++)
        t[ty + 8 * r][tx] = W[(size_t)(k0 + ty + 8 * r) * N + n0 + tx];
    __syncthreads();
    #pragma unroll
    for (int r = 0; r < 4; r++) {
        float v = t[tx][ty + 8 * r];
        __nv_bfloat16 hv = __float2bfloat16(v);
        size_t o = (size_t)(n0 + ty + 8 * r) * K + k0 + tx;
        Th[o] = hv;
        Tl[o] = __float2bfloat16(v - __bfloat162float(hv));
    }
}

// ---------------------------------------------------------------------------
// bf16x3 GEMM via mma.sync: C[M,N] = Ah/Al[M,1024] x (Bh/Bl[N,1024])^T + bias
// 128x128 CTA tile, 8 warps (2x4), 64x32 per warp, BK=32, double buffer.
// SMEM stage layout (stride 40 bf16 = 80 B per row, conflict-free frags):
//   Ah[128][40], Al[128][40], Bh[128][40], Bl[128][40]  = 40960 B / stage
// ---------------------------------------------------------------------------
#define GSTRIDE  80u          // bytes per smem row (40 bf16)
#define GMATB    10240u       // bytes per matrix tile (128 * 80)
#define GSTAGE   40960u       // bytes per stage
#define GEMM_SMEM (2 * GSTAGE)
#define NCHUNK   32           // 1024 / 32

__global__ __launch_bounds__(256) void gemm_bf16x3_kernel(int N,
    const __nv_bfloat16* __restrict__ Ah, const __nv_bfloat16* __restrict__ Al,
    const __nv_bfloat16* __restrict__ Bh, const __nv_bfloat16* __restrict__ Bl,
    const float* __restrict__ bias, float* __restrict__ C)
{
    extern __shared__ unsigned char smem[];
    const uint32_t sb = smem_u32(smem);

    const int tid  = threadIdx.x;
    const int lane = tid & 31;
    const int warp = tid >> 5;
    const int wm   = warp >> 2;          // 0..1  (64-row slab)
    const int wn   = warp & 3;           // 0..3  (32-col slab)
    const int g    = lane >> 2;          // 0..7
    const int t    = lane & 3;           // 0..3
    const int brow = blockIdx.y * 128;
    const int bcol = blockIdx.x * 128;

    float acc[4][4][4];
    #pragma unroll
    for (int i = 0; i < 4; i++)
        #pragma unroll
        for (int j = 0; j < 4; j++)
            #pragma unroll
            for (int r = 0; r < 4; r++) acc[i][j][r] = 0.f;

    auto load_chunk = [&](int c) {
        const uint32_t base = sb + (uint32_t)(c & 1) * GSTAGE;
        const int kc = c * 32;
        #pragma unroll
        for (int m = 0; m < 4; m++) {
            const __nv_bfloat16* src = (m == 0) ? Ah : (m == 1) ? Al
                                     : (m == 2) ? Bh : Bl;
            const int rb = (m < 2) ? brow : bcol;
            #pragma unroll
            for (int i = 0; i < 2; i++) {
                int u   = tid + i * 256;          // 0..511
                int row = u >> 2, q = u & 3;
                const __nv_bfloat16* gsrc =
                    src + (size_t)(rb + row) * Kn + kc + q * 8;
                uint32_t dst = base + m * GMATB + row * GSTRIDE + q * 16u;
                CP_ASYNC16(dst, gsrc);
            }
        }
        CP_COMMIT();
    };

    load_chunk(0);
    load_chunk(1);

    for (int c = 0; c < NCHUNK; c++) {
        if (c < NCHUNK - 1)
            asm volatile("cp.async.wait_group 1;" ::: "memory");
        else
            asm volatile("cp.async.wait_group 0;" ::: "memory");
        __syncthreads();

        const uint32_t base   = sb + (uint32_t)(c & 1) * GSTAGE;
        const uint32_t aoff_h = base;
        const uint32_t aoff_l = base + GMATB;
        const uint32_t boff_h = base + 2 * GMATB;
        const uint32_t boff_l = base + 3 * GMATB;

        #pragma unroll
        for (int s = 0; s < 2; s++) {
            const uint32_t kb = s * 32u + t * 4u;      // byte offset of 2 bf16
            uint32_t ah[4][4], al[4][4];
            #pragma unroll
            for (int i = 0; i < 4; i++) {
                uint32_t r0 = (uint32_t)(wm * 64 + i * 16 + g) * GSTRIDE + kb;
                ah[i][0] = *(const uint32_t*)(smem + (aoff_h - sb) + r0);
                ah[i][1] = *(const uint32_t*)(smem + (aoff_h - sb) + r0 + 8 * GSTRIDE);
                ah[i][2] = *(const uint32_t*)(smem + (aoff_h - sb) + r0 + 16);
                ah[i][3] = *(const uint32_t*)(smem + (aoff_h - sb) + r0 + 8 * GSTRIDE + 16);
                al[i][0] = *(const uint32_t*)(smem + (aoff_l - sb) + r0);
                al[i][1] = *(const uint32_t*)(smem + (aoff_l - sb) + r0 + 8 * GSTRIDE);
                al[i][2] = *(const uint32_t*)(smem + (aoff_l - sb) + r0 + 16);
                al[i][3] = *(const uint32_t*)(smem + (aoff_l - sb) + r0 + 8 * GSTRIDE + 16);
            }
            uint32_t bh[4][2], bl[4][2];
            #pragma unroll
            for (int j = 0; j < 4; j++) {
                uint32_t r0 = (uint32_t)(wn * 32 + j * 8 + g) * GSTRIDE + kb;
                bh[j][0] = *(const uint32_t*)(smem + (boff_h - sb) + r0);
                bh[j][1] = *(const uint32_t*)(smem + (boff_h - sb) + r0 + 16);
                bl[j][0] = *(const uint32_t*)(smem + (boff_l - sb) + r0);
                bl[j][1] = *(const uint32_t*)(smem + (boff_l - sb) + r0 + 16);
            }
            #pragma unroll
            for (int i = 0; i < 4; i++)
                #pragma unroll
                for (int j = 0; j < 4; j++) {
                    MMA16816(acc[i][j], ah[i], bh[j]);
                    MMA16816(acc[i][j], ah[i], bl[j]);
                    MMA16816(acc[i][j], al[i], bh[j]);
                }
        }
        __syncthreads();
        if (c + 2 < NCHUNK) load_chunk(c + 2);
    }

    // epilogue: acc -> C with bias
    #pragma unroll
    for (int i = 0; i < 4; i++) {
        const int r0 = brow + wm * 64 + i * 16 + g;
        #pragma unroll
        for (int j = 0; j < 4; j++) {
            const int col = bcol + wn * 32 + j * 8 + t * 2;
            float2 bs = *(const float2*)(bias + col);
            float2 o0, o1;
            o0.x = acc[i][j][0] + bs.x;
            o0.y = acc[i][j][1] + bs.y;
            o1.x = acc[i][j][2] + bs.x;
            o1.y = acc[i][j][3] + bs.y;
            *(float2*)(C + (size_t)r0 * N + col)       = o0;
            *(float2*)(C + (size_t)(r0 + 8) * N + col) = o1;
        }
    }
}

// ---------------------------------------------------------------------------
// RoPE on q and k inside qkv
// ---------------------------------------------------------------------------
__global__ __launch_bounds__(256) void rope_kernel(
    float* qkv, const float* __restrict__ fcos, const float* __restrict__ fsin)
{
    int idx = blockIdx.x * blockDim.x + threadIdx.x;
    int d     = idx & 31;
    int h     = (idx >> 5) & 15;
    int m     = (idx >> 9) & 4095;
    int which = idx >> 21;
    int t     = m & (Tn - 1);

    float c = fcos[t * HD2n + d];
    float s = fsin[t * HD2n + d];
    float* p = qkv + (size_t)m * N3n + which * Cn + h * HDn + d;
    float u1 = p[0];
    float u2 = p[HD2n];
    p[0]    = u1 * c - u2 * s;
    p[HD2n] = u1 * s + u2 * c;
}

// ---------------------------------------------------------------------------
// Causal flash attention (fp32 SIMT, proven from R1)
// ---------------------------------------------------------------------------
#define FA_SMEM (384 * 65 * 4)

__global__ __launch_bounds__(128) void flash_kernel(
    const float* __restrict__ qkv, float* __restrict__ out)
{
    extern __shared__ float sm[];
    float* Qs = sm;
    float* Ks = Qs + 128 * 65;
    float* Vs = Ks + 64 * 65;
    float* Ps = Vs + 64 * 65;

    const int tid = threadIdx.x;
    const int ty  = tid >> 3;
    const int tx  = tid & 7;
    const int rbase = ty * 8;
    const int cb    = tx * 8;

    const int qb = 15 - blockIdx.x;
    const int h  = blockIdx.y;
    const int b  = blockIdx.z;
    const size_t qrow0 = (size_t)b * Tn + qb * 128;
    const float scale = 0.125f;
    const float L2E = 1.44269504088896f;

    for (int i = tid; i < 128 * 16; i += 128) {
        int r = i >> 4, dg = (i & 15) * 4;
        float4 q4 = *(const float4*)(qkv + (qrow0 + r) * N3n + h * HDn + dg);
        float* dst = Qs + r * 65 + dg;
        dst[0] = q4.x * scale; dst[1] = q4.y * scale;
        dst[2] = q4.z * scale; dst[3] = q4.w * scale;
    }

    float m_i[8], l_i[8], o[8][8];
    #pragma unroll
    for (int i = 0; i < 8; i++) {
        m_i[i] = -1e30f; l_i[i] = 0.f;
        #pragma unroll
        for (int j = 0; j < 8; j++) o[i][j] = 0.f;
    }

    const int nkb = qb * 2 + 2;
    for (int kb = 0; kb < nkb; kb++) {
        __syncthreads();
        const size_t krow0 = (size_t)b * Tn + kb * 64;
        for (int i = tid; i < 64 * 16; i += 128) {
            int r = i >> 4, dg = (i & 15) * 4;
            const float* base = qkv + (krow0 + r) * N3n + Cn + h * HDn + dg;
            float4 k4 = *(const float4*)base;
            float4 v4 = *(const float4*)(base + Cn);
            float* kd = Ks + r * 65 + dg;
            kd[0] = k4.x; kd[1] = k4.y; kd[2] = k4.z; kd[3] = k4.w;
            float* vd = Vs + r * 65 + dg;
            vd[0] = v4.x; vd[1] = v4.y; vd[2] = v4.z; vd[3] = v4.w;
        }
        __syncthreads();

        float s[8][8];
        #pragma unroll
        for (int i = 0; i < 8; i++)
            #pragma unroll
            for (int j = 0; j < 8; j++) s[i][j] = 0.f;

        #pragma unroll 8
        for (int d = 0; d < 64; d++) {
            float ar[8], br[8];
            #pragma unroll
            for (int i = 0; i < 8; i++) ar[i] = Qs[(rbase + i) * 65 + d];
            #pragma unroll
            for (int j = 0; j < 8; j++) br[j] = Ks[(cb + j) * 65 + d];
            #pragma unroll
            for (int i = 0; i < 8; i++)
                #pragma unroll
                for (int j = 0; j < 8; j++)
                    s[i][j] += ar[i] * br[j];
        }

        if (kb >= 2 * qb) {
            #pragma unroll
            for (int i = 0; i < 8; i++)
                #pragma unroll
                for (int j = 0; j < 8; j++)
                    if (kb * 64 + cb + j > qb * 128 + rbase + i)
                        s[i][j] = -1e30f;
        }

        #pragma unroll
        for (int i = 0; i < 8; i++) {
            float mx = s[i][0];
            #pragma unroll
            for (int j = 1; j < 8; j++) mx = fmaxf(mx, s[i][j]);
            mx = fmaxf(mx, __shfl_xor_sync(0xffffffffu, mx, 1));
            mx = fmaxf(mx, __shfl_xor_sync(0xffffffffu, mx, 2));
            mx = fmaxf(mx, __shfl_xor_sync(0xffffffffu, mx, 4));
            float mnew  = fmaxf(m_i[i], mx);
            float alpha = exp2f((m_i[i] - mnew) * L2E);
            m_i[i] = mnew;
            float rs = 0.f;
            #pragma unroll
            for (int j = 0; j < 8; j++) {
                float p = exp2f((s[i][j] - mnew) * L2E);
                s[i][j] = p;
                rs += p;
            }
            rs += __shfl_xor_sync(0xffffffffu, rs, 1);
            rs += __shfl_xor_sync(0xffffffffu, rs, 2);
            rs += __shfl_xor_sync(0xffffffffu, rs, 4);
            l_i[i] = l_i[i] * alpha + rs;
            #pragma unroll
            for (int j = 0; j < 8; j++) o[i][j] *= alpha;
            #pragma unroll
            for (int j = 0; j < 8; j++)
                Ps[(rbase + i) * 65 + cb + j] = s[i][j];
        }
        __syncthreads();

        #pragma unroll 4
        for (int c = 0; c < 64; c++) {
            float pr[8], vr[8];
            #pragma unroll
            for (int i = 0; i < 8; i++) pr[i] = Ps[(rbase + i) * 65 + c];
            #pragma unroll
            for (int j = 0; j < 8; j++) vr[j] = Vs[c * 65 + cb + j];
            #pragma unroll
            for (int i = 0; i < 8; i++)
                #pragma unroll
                for (int j = 0; j < 8; j++)
                    o[i][j] += pr[i] * vr[j];
        }
    }

    #pragma unroll
    for (int i = 0; i < 8; i++) {
        float inv = 1.0f / l_i[i];
        float* dst = out + (qrow0 + rbase + i) * Cn + h * HDn + cb;
        float4 o0, o1;
        o0.x = o[i][0] * inv; o0.y = o[i][1] * inv;
        o0.z = o[i][2] * inv; o0.w = o[i][3] * inv;
        o1.x = o[i][4] * inv; o1.y = o[i][5] * inv;
        o1.z = o[i][6] * inv; o1.w = o[i][7] * inv;
        *(float4*)dst       = o0;
        *(float4*)(dst + 4) = o1;
    }
}

// ---------------------------------------------------------------------------
extern "C" void kernel_launch(void* const* d_in, const int* in_sizes, int n_in,
                              void* d_out, int out_size)
{
    const float* x     = (const float*)d_in[0];
    const float* fcos  = (const float*)d_in[1];
    const float* fsin  = (const float*)d_in[2];
    const float* Wqkv  = (const float*)d_in[3];
    const float* bqkv  = (const float*)d_in[4];
    const float* Wproj = (const float*)d_in[5];
    const float* bproj = (const float*)d_in[6];
    float* out = (float*)d_out;

    unsigned char* pool = nullptr;
    cudaGetSymbolAddress((void**)&pool, g_pool);
    float* qkv = (float*)(pool + OFF_QKV);
    float* att = (float*)(pool + OFF_ATT);
    __nv_bfloat16* xh  = (__nv_bfloat16*)(pool + OFF_XH);
    __nv_bfloat16* xl  = (__nv_bfloat16*)(pool + OFF_XL);
    __nv_bfloat16* wqh = (__nv_bfloat16*)(pool + OFF_WQH);
    __nv_bfloat16* wql = (__nv_bfloat16*)(pool + OFF_WQL);
    __nv_bfloat16* wph = (__nv_bfloat16*)(pool + OFF_WPH);
    __nv_bfloat16* wpl = (__nv_bfloat16*)(pool + OFF_WPL);
    __nv_bfloat16* ah  = (__nv_bfloat16*)(pool + OFF_AH);
    __nv_bfloat16* al  = (__nv_bfloat16*)(pool + OFF_AL);

    cudaFuncSetAttribute(flash_kernel,
                         cudaFuncAttributeMaxDynamicSharedMemorySize, FA_SMEM);
    cudaFuncSetAttribute(gemm_bf16x3_kernel,
                         cudaFuncAttributeMaxDynamicSharedMemorySize, GEMM_SMEM);

    // prep: split x; transpose+split weights
    split_kernel<<<(Mn * Cn) / 256, 256>>>(x, xh, xl, Mn * Cn);
    transpose_split_kernel<<<dim3(N3n / 32, Kn / 32), 256>>>(Wqkv, wqh, wql, Kn, N3n);
    transpose_split_kernel<<<dim3(Cn / 32, Kn / 32), 256>>>(Wproj, wph, wpl, Kn, Cn);

    // 1) qkv = x @ Wqkv + bqkv   (mma.sync bf16x3)
    gemm_bf16x3_kernel<<<dim3(N3n / 128, Mn / 128), 256, GEMM_SMEM>>>(
        N3n, xh, xl, wqh, wql, bqkv, qkv);

    // 2) RoPE
    rope_kernel<<<(Mn * Hn * HD2n * 2) / 256, 256>>>(qkv, fcos, fsin);

    // 3) flash attention (fp32)
    flash_kernel<<<dim3(Tn / 128, Hn, Bn), 128, FA_SMEM>>>(qkv, att);

    // 4) split att; out = att @ Wproj + bproj
    split_kernel<<<(Mn * Cn) / 256, 256>>>(att, ah, al, Mn * Cn);
    gemm_bf16x3_kernel<<<dim3(Cn / 128, Mn / 128), 256, GEMM_SMEM>>>(
        Cn, ah, al, wph, wpl, bproj, out);
}

// round 6
// speedup vs baseline: 2.3622x; 1.6829x over previous
#include <cuda_runtime.h>
#include <cuda_bf16.h>
#include <cstdint>
#include <math.h>

#define Bn   2
#define Tn   2048
#define Cn   1024
#define Hn   16
#define HDn  64
#define HD2n 32
#define Mn   (Bn * Tn)          // 4096
#define N3n  (3 * Cn)           // 3072
#define Kn   1024

// ---------------------------------------------------------------------------
// Scratch pool
// ---------------------------------------------------------------------------
#define OFF_QKV   0ull                                   // fp32 [4096][3072]
#define OFF_XH    (OFF_QKV   + 50331648ull)              // bf16 [4096][1024]
#define OFF_XL    (OFF_XH    + 8388608ull)
#define OFF_WQH   (OFF_XL    + 8388608ull)               // bf16 [3072][1024]
#define OFF_WQL   (OFF_WQH   + 6291456ull)
#define OFF_WPH   (OFF_WQL   + 6291456ull)               // bf16 [1024][1024]
#define OFF_WPL   (OFF_WPH   + 2097152ull)
#define OFF_AH    (OFF_WPL   + 2097152ull)               // bf16 [4096][1024]
#define OFF_AL    (OFF_AH    + 8388608ull)
#define OFF_QH    (OFF_AL    + 8388608ull)               // bf16 [32][2048][64]
#define OFF_QL    (OFF_QH    + 8388608ull)
#define OFF_KH    (OFF_QL    + 8388608ull)
#define OFF_KL    (OFF_KH    + 8388608ull)
#define OFF_VH    (OFF_KL    + 8388608ull)               // bf16 [32][64][2048]
#define OFF_VL    (OFF_VH    + 8388608ull)
#define POOL_SZ   (OFF_VL    + 8388608ull)

__device__ __align__(1024) unsigned char g_pool[POOL_SZ];

// ---------------------------------------------------------------------------
// helpers
// ---------------------------------------------------------------------------
#define MMA16816(d, a, b) \
    asm volatile( \
        "mma.sync.aligned.m16n8k16.row.col.f32.bf16.bf16.f32 " \
        "{%0,%1,%2,%3}, {%4,%5,%6,%7}, {%8,%9}, {%0,%1,%2,%3};" \
        : "+f"((d)[0]), "+f"((d)[1]), "+f"((d)[2]), "+f"((d)[3]) \
        : "r"((a)[0]), "r"((a)[1]), "r"((a)[2]), "r"((a)[3]), \
          "r"((b)[0]), "r"((b)[1]))

#define CP_ASYNC16(dst, src) \
    asm volatile("cp.async.cg.shared.global [%0], [%1], 16;" \
                 :: "r"(dst), "l"(src) : "memory")
#define CP_COMMIT() asm volatile("cp.async.commit_group;" ::: "memory")

__device__ __forceinline__ uint32_t smem_u32(const void* p) {
    uint32_t a;
    asm("{ .reg .u64 t; cvta.to.shared.u64 t, %1; cvt.u32.u64 %0, t; }"
        : "=r"(a) : "l"(p));
    return a;
}

__device__ __forceinline__ uint32_t lds32(uint32_t a) {
    uint32_t v;
    asm volatile("ld.shared.b32 %0, [%1];" : "=r"(v) : "r"(a));
    return v;
}

__device__ __forceinline__ uint32_t pack_bf2(float x, float y) {
    __nv_bfloat162 v = __floats2bfloat162_rn(x, y);
    return *(uint32_t*)&v;
}

// ---------------------------------------------------------------------------
// Split fp32 -> bf16 hi/lo
// ---------------------------------------------------------------------------
__global__ __launch_bounds__(256) void split_kernel(
    const float* __restrict__ in, __nv_bfloat16* __restrict__ h,
    __nv_bfloat16* __restrict__ l, int n)
{
    int i = blockIdx.x * 256 + threadIdx.x;
    if (i < n) {
        float v = in[i];
        __nv_bfloat16 hv = __float2bfloat16(v);
        h[i] = hv;
        l[i] = __float2bfloat16(v - __bfloat162float(hv));
    }
}

// ---------------------------------------------------------------------------
// Transpose + split: W[K][N] fp32 -> Th, Tl [N][K] bf16
// ---------------------------------------------------------------------------
__global__ __launch_bounds__(256) void transpose_split_kernel(
    const float* __restrict__ W, __nv_bfloat16* __restrict__ Th,
    __nv_bfloat16* __restrict__ Tl, int K, int N)
{
    __shared__ float t[32][33];
    int n0 = blockIdx.x * 32, k0 = blockIdx.y * 32;
    int tx = threadIdx.x & 31, ty = threadIdx.x >> 5;
    #pragma unroll
    for (int r = 0; r < 4; r++)
        t[ty + 8 * r][tx] = W[(size_t)(k0 + ty + 8 * r) * N + n0 + tx];
    __syncthreads();
    #pragma unroll
    for (int r = 0; r < 4; r++) {
        float v = t[tx][ty + 8 * r];
        __nv_bfloat16 hv = __float2bfloat16(v);
        size_t o = (size_t)(n0 + ty + 8 * r) * K + k0 + tx;
        Th[o] = hv;
        Tl[o] = __float2bfloat16(v - __bfloat162float(hv));
    }
}

// ---------------------------------------------------------------------------
// bf16x3 GEMM (unchanged from R3)
// ---------------------------------------------------------------------------
#define GSTRIDE  80u
#define GMATB    10240u
#define GSTAGE   40960u
#define GEMM_SMEM (2 * GSTAGE)
#define NCHUNK   32

__global__ __launch_bounds__(256) void gemm_bf16x3_kernel(int N,
    const __nv_bfloat16* __restrict__ Ah, const __nv_bfloat16* __restrict__ Al,
    const __nv_bfloat16* __restrict__ Bh, const __nv_bfloat16* __restrict__ Bl,
    const float* __restrict__ bias, float* __restrict__ C)
{
    extern __shared__ unsigned char smem[];
    const uint32_t sb = smem_u32(smem);

    const int tid  = threadIdx.x;
    const int lane = tid & 31;
    const int warp = tid >> 5;
    const int wm   = warp >> 2;
    const int wn   = warp & 3;
    const int g    = lane >> 2;
    const int t    = lane & 3;
    const int brow = blockIdx.y * 128;
    const int bcol = blockIdx.x * 128;

    float acc[4][4][4];
    #pragma unroll
    for (int i = 0; i < 4; i++)
        #pragma unroll
        for (int j = 0; j < 4; j++)
            #pragma unroll
            for (int r = 0; r < 4; r++) acc[i][j][r] = 0.f;

    auto load_chunk = [&](int c) {
        const uint32_t base = sb + (uint32_t)(c & 1) * GSTAGE;
        const int kc = c * 32;
        #pragma unroll
        for (int m = 0; m < 4; m++) {
            const __nv_bfloat16* src = (m == 0) ? Ah : (m == 1) ? Al
                                     : (m == 2) ? Bh : Bl;
            const int rb = (m < 2) ? brow : bcol;
            #pragma unroll
            for (int i = 0; i < 2; i++) {
                int u   = tid + i * 256;
                int row = u >> 2, q = u & 3;
                const __nv_bfloat16* gsrc =
                    src + (size_t)(rb + row) * Kn + kc + q * 8;
                uint32_t dst = base + m * GMATB + row * GSTRIDE + q * 16u;
                CP_ASYNC16(dst, gsrc);
            }
        }
        CP_COMMIT();
    };

    load_chunk(0);
    load_chunk(1);

    for (int c = 0; c < NCHUNK; c++) {
        if (c < NCHUNK - 1)
            asm volatile("cp.async.wait_group 1;" ::: "memory");
        else
            asm volatile("cp.async.wait_group 0;" ::: "memory");
        __syncthreads();

        const uint32_t base = sb + (uint32_t)(c & 1) * GSTAGE;
        const uint32_t aoff_h = base - sb;
        const uint32_t aoff_l = aoff_h + GMATB;
        const uint32_t boff_h = aoff_h + 2 * GMATB;
        const uint32_t boff_l = aoff_h + 3 * GMATB;

        #pragma unroll
        for (int s = 0; s < 2; s++) {
            const uint32_t kb = s * 32u + t * 4u;
            uint32_t ah[4][4], al[4][4];
            #pragma unroll
            for (int i = 0; i < 4; i++) {
                uint32_t r0 = (uint32_t)(wm * 64 + i * 16 + g) * GSTRIDE + kb;
                ah[i][0] = *(const uint32_t*)(smem + aoff_h + r0);
                ah[i][1] = *(const uint32_t*)(smem + aoff_h + r0 + 8 * GSTRIDE);
                ah[i][2] = *(const uint32_t*)(smem + aoff_h + r0 + 16);
                ah[i][3] = *(const uint32_t*)(smem + aoff_h + r0 + 8 * GSTRIDE + 16);
                al[i][0] = *(const uint32_t*)(smem + aoff_l + r0);
                al[i][1] = *(const uint32_t*)(smem + aoff_l + r0 + 8 * GSTRIDE);
                al[i][2] = *(const uint32_t*)(smem + aoff_l + r0 + 16);
                al[i][3] = *(const uint32_t*)(smem + aoff_l + r0 + 8 * GSTRIDE + 16);
            }
            uint32_t bh[4][2], bl[4][2];
            #pragma unroll
            for (int j = 0; j < 4; j++) {
                uint32_t r0 = (uint32_t)(wn * 32 + j * 8 + g) * GSTRIDE + kb;
                bh[j][0] = *(const uint32_t*)(smem + boff_h + r0);
                bh[j][1] = *(const uint32_t*)(smem + boff_h + r0 + 16);
                bl[j][0] = *(const uint32_t*)(smem + boff_l + r0);
                bl[j][1] = *(const uint32_t*)(smem + boff_l + r0 + 16);
            }
            #pragma unroll
            for (int i = 0; i < 4; i++)
                #pragma unroll
                for (int j = 0; j < 4; j++) {
                    MMA16816(acc[i][j], ah[i], bh[j]);
                    MMA16816(acc[i][j], ah[i], bl[j]);
                    MMA16816(acc[i][j], al[i], bh[j]);
                }
        }
        __syncthreads();
        if (c + 2 < NCHUNK) load_chunk(c + 2);
    }

    #pragma unroll
    for (int i = 0; i < 4; i++) {
        const int r0 = brow + wm * 64 + i * 16 + g;
        #pragma unroll
        for (int j = 0; j < 4; j++) {
            const int col = bcol + wn * 32 + j * 8 + t * 2;
            float2 bs = *(const float2*)(bias + col);
            float2 o0, o1;
            o0.x = acc[i][j][0] + bs.x;
            o0.y = acc[i][j][1] + bs.y;
            o1.x = acc[i][j][2] + bs.x;
            o1.y = acc[i][j][3] + bs.y;
            *(float2*)(C + (size_t)r0 * N + col)       = o0;
            *(float2*)(C + (size_t)(r0 + 8) * N + col) = o1;
        }
    }
}

// ---------------------------------------------------------------------------
// Prep A: RoPE + scale(Q) + hi/lo split of Q,K -> [bh][T][64] bf16
// one thread per (b,t,h,d), d in 0..31
// ---------------------------------------------------------------------------
__global__ __launch_bounds__(256) void rope_split_qk_kernel(
    const float* __restrict__ qkv,
    const float* __restrict__ fcos, const float* __restrict__ fsin,
    __nv_bfloat16* __restrict__ Qh, __nv_bfloat16* __restrict__ Ql,
    __nv_bfloat16* __restrict__ Kh, __nv_bfloat16* __restrict__ Kl)
{
    int i = blockIdx.x * 256 + threadIdx.x;     // 0 .. 2*2048*16*32-1
    int d  = i & 31;
    int h  = (i >> 5) & 15;
    int tt = (i >> 9) & 2047;
    int b  = i >> 20;

    float c = fcos[tt * HD2n + d];
    float s = fsin[tt * HD2n + d];

    const float* qp = qkv + ((size_t)(b * Tn + tt)) * N3n + h * HDn + d;
    float q1 = qp[0],    q2 = qp[HD2n];
    float k1 = qp[Cn],   k2 = qp[Cn + HD2n];

    float rq1 = (q1 * c - q2 * s) * 0.125f;
    float rq2 = (q1 * s + q2 * c) * 0.125f;
    float rk1 = k1 * c - k2 * s;
    float rk2 = k1 * s + k2 * c;

    size_t o = ((size_t)(b * Hn + h) * Tn + tt) * HDn + d;
    __nv_bfloat16 v;
    v = __float2bfloat16(rq1); Qh[o] = v;
    Ql[o] = __float2bfloat16(rq1 - __bfloat162float(v));
    v = __float2bfloat16(rq2); Qh[o + HD2n] = v;
    Ql[o + HD2n] = __float2bfloat16(rq2 - __bfloat162float(v));
    v = __float2bfloat16(rk1); Kh[o] = v;
    Kl[o] = __float2bfloat16(rk1 - __bfloat162float(v));
    v = __float2bfloat16(rk2); Kh[o + HD2n] = v;
    Kl[o + HD2n] = __float2bfloat16(rk2 - __bfloat162float(v));
}

// ---------------------------------------------------------------------------
// Prep B: V hi/lo split + transpose -> [bh][64 hd][2048 T] bf16
// grid (T/64, H, B), 256 threads
// ---------------------------------------------------------------------------
__global__ __launch_bounds__(256) void v_split_t_kernel(
    const float* __restrict__ qkv,
    __nv_bfloat16* __restrict__ Vh, __nv_bfloat16* __restrict__ Vl)
{
    __shared__ float vs[64][65];
    int tb = blockIdx.x, h = blockIdx.y, b = blockIdx.z;
    int tid = threadIdx.x;
    int r = tid >> 2, cq = (tid & 3) * 16;
    const float* src = qkv + ((size_t)(b * Tn + tb * 64 + r)) * N3n
                       + 2 * Cn + h * HDn + cq;
    #pragma unroll
    for (int i = 0; i < 4; i++) {
        float4 v4 = *(const float4*)(src + i * 4);
        vs[r][cq + i * 4 + 0] = v4.x;
        vs[r][cq + i * 4 + 1] = v4.y;
        vs[r][cq + i * 4 + 2] = v4.z;
        vs[r][cq + i * 4 + 3] = v4.w;
    }
    __syncthreads();
    // write transposed: hd = r, key col = cq..cq+15
    size_t base = ((size_t)(b * Hn + h) * HDn + r) * Tn + tb * 64 + cq;
    #pragma unroll
    for (int i = 0; i < 16; i++) {
        float v = vs[cq + i][r];
        __nv_bfloat16 hv = __float2bfloat16(v);
        Vh[base + i] = hv;
        Vl[base + i] = __float2bfloat16(v - __bfloat162float(hv));
    }
}

// ---------------------------------------------------------------------------
// Flash attention via mma.sync bf16x3.
// 256 thr / 8 warps; warp w owns query rows w*16..w*16+15 of a 128-row tile.
// smem: Qh[128][72], Ql[128][72]; 2 stages of {Kh,Kl,Vh,Vl}[64][72] each.
// ---------------------------------------------------------------------------
#define FSTR      144u                 // 72 bf16 per row
#define FQ_BYTES  (128u * FSTR)        // 18432
#define FK_BYTES  (64u * FSTR)         // 9216
#define FSTAGE    (4u * FK_BYTES)      // 36864
#define FA2_SMEM  (2u * FQ_BYTES + 2u * FSTAGE)   // 110592

__global__ __launch_bounds__(256) void flash_mma_kernel(
    const __nv_bfloat16* __restrict__ Qh_, const __nv_bfloat16* __restrict__ Ql_,
    const __nv_bfloat16* __restrict__ Kh_, const __nv_bfloat16* __restrict__ Kl_,
    const __nv_bfloat16* __restrict__ Vh_, const __nv_bfloat16* __restrict__ Vl_,
    __nv_bfloat16* __restrict__ ah, __nv_bfloat16* __restrict__ al)
{
    extern __shared__ unsigned char smem[];
    const uint32_t sb = smem_u32(smem);

    const int tid  = threadIdx.x;
    const int lane = tid & 31;
    const int w    = tid >> 5;
    const int g    = lane >> 2;
    const int t    = lane & 3;

    const int qb = 15 - blockIdx.x;
    const int h  = blockIdx.y;
    const int b  = blockIdx.z;
    const int bh = b * Hn + h;
    const size_t qk_base = (size_t)bh * Tn * HDn;
    const size_t v_base  = (size_t)bh * HDn * Tn;
    const float L2E = 1.44269504088896f;

    // Q tiles (group 0)
    #pragma unroll
    for (int i = 0; i < 4; i++) {
        int u = tid + i * 256;
        int row = u >> 3, q = u & 7;
        size_t gof = qk_base + (size_t)(qb * 128 + row) * HDn + q * 8;
        CP_ASYNC16(sb + row * FSTR + q * 16u, Qh_ + gof);
        CP_ASYNC16(sb + FQ_BYTES + row * FSTR + q * 16u, Ql_ + gof);
    }
    CP_COMMIT();

    auto load_kv = [&](int kb) {
        uint32_t base = sb + 2u * FQ_BYTES + (uint32_t)(kb & 1) * FSTAGE;
        #pragma unroll
        for (int i = 0; i < 2; i++) {
            int u = tid + i * 256;
            int row = u >> 3, q = u & 7;
            size_t kof = qk_base + (size_t)(kb * 64 + row) * HDn + q * 8;
            size_t vof = v_base + (size_t)row * Tn + kb * 64 + q * 8;
            CP_ASYNC16(base + row * FSTR + q * 16u, Kh_ + kof);
            CP_ASYNC16(base + FK_BYTES + row * FSTR + q * 16u, Kl_ + kof);
            CP_ASYNC16(base + 2u * FK_BYTES + row * FSTR + q * 16u, Vh_ + vof);
            CP_ASYNC16(base + 3u * FK_BYTES + row * FSTR + q * 16u, Vl_ + vof);
        }
        CP_COMMIT();
    };

    float o[8][4];
    #pragma unroll
    for (int j = 0; j < 8; j++)
        #pragma unroll
        for (int e = 0; e < 4; e++) o[j][e] = 0.f;
    float m_i[2] = {-1e30f, -1e30f};
    float l_i[2] = {0.f, 0.f};

    const int row_hi = qb * 128 + w * 16 + 15;
    const int nkb = 2 * qb + 2;

    load_kv(0);

    for (int kb = 0; kb < nkb; kb++) {
        if (kb + 1 < nkb) {
            load_kv(kb + 1);
            asm volatile("cp.async.wait_group 1;" ::: "memory");
        } else {
            asm volatile("cp.async.wait_group 0;" ::: "memory");
        }
        __syncthreads();

        const bool active = (kb * 64 <= row_hi);
        if (active) {
            const uint32_t kbase = sb + 2u * FQ_BYTES + (uint32_t)(kb & 1) * FSTAGE;

            // ---- S = Q K^T (3 terms) ----
            float s[8][4];
            #pragma unroll
            for (int j = 0; j < 8; j++)
                #pragma unroll
                for (int e = 0; e < 4; e++) s[j][e] = 0.f;

            #pragma unroll
            for (int kk = 0; kk < 4; kk++) {
                uint32_t ar = sb + (uint32_t)(w * 16 + g) * FSTR + 32u * kk + 4u * t;
                uint32_t aQh[4], aQl[4];
                aQh[0] = lds32(ar);
                aQh[1] = lds32(ar + 8 * FSTR);
                aQh[2] = lds32(ar + 16);
                aQh[3] = lds32(ar + 8 * FSTR + 16);
                aQl[0] = lds32(ar + FQ_BYTES);
                aQl[1] = lds32(ar + FQ_BYTES + 8 * FSTR);
                aQl[2] = lds32(ar + FQ_BYTES + 16);
                aQl[3] = lds32(ar + FQ_BYTES + 8 * FSTR + 16);
                #pragma unroll
                for (int j = 0; j < 8; j++) {
                    uint32_t br = kbase + (uint32_t)(j * 8 + g) * FSTR + 32u * kk + 4u * t;
                    uint32_t bKh[2], bKl[2];
                    bKh[0] = lds32(br);            bKh[1] = lds32(br + 16);
                    bKl[0] = lds32(br + FK_BYTES); bKl[1] = lds32(br + FK_BYTES + 16);
                    MMA16816(s[j], aQh, bKh);
                    MMA16816(s[j], aQh, bKl);
                    MMA16816(s[j], aQl, bKh);
                }
            }

            // ---- causal mask ----
            if (kb * 64 + 63 > qb * 128 + w * 16) {
                #pragma unroll
                for (int j = 0; j < 8; j++)
                    #pragma unroll
                    for (int e = 0; e < 4; e++) {
                        int col = kb * 64 + j * 8 + 2 * t + (e & 1);
                        int row = qb * 128 + w * 16 + g + ((e >> 1) << 3);
                        if (col > row) s[j][e] = -1e30f;
                    }
            }

            // ---- online softmax (per row-slot u) ----
            #pragma unroll
            for (int u = 0; u < 2; u++) {
                float mx = -1e30f;
                #pragma unroll
                for (int j = 0; j < 8; j++)
                    mx = fmaxf(mx, fmaxf(s[j][2 * u], s[j][2 * u + 1]));
                mx = fmaxf(mx, __shfl_xor_sync(0xffffffffu, mx, 1));
                mx = fmaxf(mx, __shfl_xor_sync(0xffffffffu, mx, 2));
                float mnew  = fmaxf(m_i[u], mx);
                float alpha = exp2f((m_i[u] - mnew) * L2E);
                m_i[u] = mnew;
                float rs = 0.f;
                #pragma unroll
                for (int j = 0; j < 8; j++) {
                    float p0 = exp2f((s[j][2 * u]     - mnew) * L2E);
                    float p1 = exp2f((s[j][2 * u + 1] - mnew) * L2E);
                    s[j][2 * u] = p0; s[j][2 * u + 1] = p1;
                    rs += p0 + p1;
                }
                rs += __shfl_xor_sync(0xffffffffu, rs, 1);
                rs += __shfl_xor_sync(0xffffffffu, rs, 2);
                l_i[u] = l_i[u] * alpha + rs;
                #pragma unroll
                for (int j = 0; j < 8; j++) {
                    o[j][2 * u]     *= alpha;
                    o[j][2 * u + 1] *= alpha;
                }
            }

            // ---- O += P V (3 terms), P rebuilt from S fragments ----
            const uint32_t vbase = kbase + 2u * FK_BYTES;
            #pragma unroll
            for (int kk = 0; kk < 4; kk++) {
                const int n0 = 2 * kk, n1 = 2 * kk + 1;
                uint32_t aPh[4], aPl[4];
                {
                    float p00 = s[n0][0], p01 = s[n0][1];
                    float p02 = s[n0][2], p03 = s[n0][3];
                    float p10 = s[n1][0], p11 = s[n1][1];
                    float p12 = s[n1][2], p13 = s[n1][3];
                    __nv_bfloat16 h00 = __float2bfloat16(p00);
                    __nv_bfloat16 h01 = __float2bfloat16(p01);
                    __nv_bfloat16 h02 = __float2bfloat16(p02);
                    __nv_bfloat16 h03 = __float2bfloat16(p03);
                    __nv_bfloat16 h10 = __float2bfloat16(p10);
                    __nv_bfloat16 h11 = __float2bfloat16(p11);
                    __nv_bfloat16 h12 = __float2bfloat16(p12);
                    __nv_bfloat16 h13 = __float2bfloat16(p13);
                    aPh[0] = ((uint32_t)*(uint16_t*)&h01 << 16) | *(uint16_t*)&h00;
                    aPh[1] = ((uint32_t)*(uint16_t*)&h03 << 16) | *(uint16_t*)&h02;
                    aPh[2] = ((uint32_t)*(uint16_t*)&h11 << 16) | *(uint16_t*)&h10;
                    aPh[3] = ((uint32_t)*(uint16_t*)&h13 << 16) | *(uint16_t*)&h12;
                    aPl[0] = pack_bf2(p00 - __bfloat162float(h00),
                                      p01 - __bfloat162float(h01));
                    aPl[1] = pack_bf2(p02 - __bfloat162float(h02),
                                      p03 - __bfloat162float(h03));
                    aPl[2] = pack_bf2(p10 - __bfloat162float(h10),
                                      p11 - __bfloat162float(h11));
                    aPl[3] = pack_bf2(p12 - __bfloat162float(h12),
                                      p13 - __bfloat162float(h13));
                }
                #pragma unroll
                for (int j = 0; j < 8; j++) {
                    uint32_t br = vbase + (uint32_t)(j * 8 + g) * FSTR + 32u * kk + 4u * t;
                    uint32_t bVh[2], bVl[2];
                    bVh[0] = lds32(br);            bVh[1] = lds32(br + 16);
                    bVl[0] = lds32(br + FK_BYTES); bVl[1] = lds32(br + FK_BYTES + 16);
                    MMA16816(o[j], aPh, bVh);
                    MMA16816(o[j], aPl, bVh);
                    MMA16816(o[j], aPh, bVl);
                }
            }
        }
        __syncthreads();
    }

    // ---- epilogue: normalize, split hi/lo, write ah/al ----
    #pragma unroll
    for (int u = 0; u < 2; u++) {
        float inv = 1.0f / l_i[u];
        int row = b * Tn + qb * 128 + w * 16 + u * 8 + g;
        #pragma unroll
        for (int j = 0; j < 8; j++) {
            float p0 = o[j][2 * u] * inv;
            float p1 = o[j][2 * u + 1] * inv;
            __nv_bfloat16 h0 = __float2bfloat16(p0);
            __nv_bfloat16 h1 = __float2bfloat16(p1);
            uint32_t hi = ((uint32_t)*(uint16_t*)&h1 << 16) | *(uint16_t*)&h0;
            uint32_t lo = pack_bf2(p0 - __bfloat162float(h0),
                                   p1 - __bfloat162float(h1));
            size_t off = (size_t)row * Cn + h * HDn + j * 8 + 2 * t;
            *(uint32_t*)(ah + off) = hi;
            *(uint32_t*)(al + off) = lo;
        }
    }
}

// ---------------------------------------------------------------------------
extern "C" void kernel_launch(void* const* d_in, const int* in_sizes, int n_in,
                              void* d_out, int out_size)
{
    const float* x     = (const float*)d_in[0];
    const float* fcos  = (const float*)d_in[1];
    const float* fsin  = (const float*)d_in[2];
    const float* Wqkv  = (const float*)d_in[3];
    const float* bqkv  = (const float*)d_in[4];
    const float* Wproj = (const float*)d_in[5];
    const float* bproj = (const float*)d_in[6];
    float* out = (float*)d_out;

    unsigned char* pool = nullptr;
    cudaGetSymbolAddress((void**)&pool, g_pool);
    float* qkv = (float*)(pool + OFF_QKV);
    __nv_bfloat16* xh  = (__nv_bfloat16*)(pool + OFF_XH);
    __nv_bfloat16* xl  = (__nv_bfloat16*)(pool + OFF_XL);
    __nv_bfloat16* wqh = (__nv_bfloat16*)(pool + OFF_WQH);
    __nv_bfloat16* wql = (__nv_bfloat16*)(pool + OFF_WQL);
    __nv_bfloat16* wph = (__nv_bfloat16*)(pool + OFF_WPH);
    __nv_bfloat16* wpl = (__nv_bfloat16*)(pool + OFF_WPL);
    __nv_bfloat16* ah  = (__nv_bfloat16*)(pool + OFF_AH);
    __nv_bfloat16* al  = (__nv_bfloat16*)(pool + OFF_AL);
    __nv_bfloat16* qh  = (__nv_bfloat16*)(pool + OFF_QH);
    __nv_bfloat16* ql  = (__nv_bfloat16*)(pool + OFF_QL);
    __nv_bfloat16* kh  = (__nv_bfloat16*)(pool + OFF_KH);
    __nv_bfloat16* kl  = (__nv_bfloat16*)(pool + OFF_KL);
    __nv_bfloat16* vh  = (__nv_bfloat16*)(pool + OFF_VH);
    __nv_bfloat16* vl  = (__nv_bfloat16*)(pool + OFF_VL);

    cudaFuncSetAttribute(gemm_bf16x3_kernel,
                         cudaFuncAttributeMaxDynamicSharedMemorySize, GEMM_SMEM);
    cudaFuncSetAttribute(flash_mma_kernel,
                         cudaFuncAttributeMaxDynamicSharedMemorySize, FA2_SMEM);

    // prep
    split_kernel<<<(Mn * Cn) / 256, 256>>>(x, xh, xl, Mn * Cn);
    transpose_split_kernel<<<dim3(N3n / 32, Kn / 32), 256>>>(Wqkv, wqh, wql, Kn, N3n);
    transpose_split_kernel<<<dim3(Cn / 32, Kn / 32), 256>>>(Wproj, wph, wpl, Kn, Cn);

    // 1) qkv = x @ Wqkv + bqkv
    gemm_bf16x3_kernel<<<dim3(N3n / 128, Mn / 128), 256, GEMM_SMEM>>>(
        N3n, xh, xl, wqh, wql, bqkv, qkv);

    // 2) RoPE + split Q,K ; split+transpose V
    rope_split_qk_kernel<<<(Bn * Tn * Hn * 32) / 256, 256>>>(
        qkv, fcos, fsin, qh, ql, kh, kl);
    v_split_t_kernel<<<dim3(Tn / 64, Hn, Bn), 256>>>(qkv, vh, vl);

    // 3) flash attention (mma) -> ah/al bf16 hi/lo
    flash_mma_kernel<<<dim3(Tn / 128, Hn, Bn), 256, FA2_SMEM>>>(
        qh, ql, kh, kl, vh, vl, ah, al);

    // 4) out = att @ Wproj + bproj
    gemm_bf16x3_kernel<<<dim3(Cn / 128, Mn / 128), 256, GEMM_SMEM>>>(
        Cn, ah, al, wph, wpl, bproj, out);
}

// round 7
// speedup vs baseline: 2.3815x; 1.0082x over previous
#include <cuda_runtime.h>
#include <cuda_bf16.h>
#include <cstdint>
#include <math.h>

#define Bn   2
#define Tn   2048
#define Cn   1024
#define Hn   16
#define HDn  64
#define HD2n 32
#define Mn   (Bn * Tn)          // 4096
#define N3n  (3 * Cn)           // 3072
#define Kn   1024

// ---------------------------------------------------------------------------
// Scratch pool
// ---------------------------------------------------------------------------
#define OFF_QKV   0ull                                   // fp32 [4096][3072]
#define OFF_XH    (OFF_QKV   + 50331648ull)              // bf16 [4096][1024]
#define OFF_XL    (OFF_XH    + 8388608ull)
#define OFF_WQH   (OFF_XL    + 8388608ull)               // bf16 [3072][1024]
#define OFF_WQL   (OFF_WQH   + 6291456ull)
#define OFF_WPH   (OFF_WQL   + 6291456ull)               // bf16 [1024][1024]
#define OFF_WPL   (OFF_WPH   + 2097152ull)
#define OFF_AH    (OFF_WPL   + 2097152ull)               // bf16 [4096][1024]
#define OFF_AL    (OFF_AH    + 8388608ull)
#define OFF_QH    (OFF_AL    + 8388608ull)               // bf16 [32][2048][64]
#define OFF_QL    (OFF_QH    + 8388608ull)
#define OFF_KH    (OFF_QL    + 8388608ull)
#define OFF_KL    (OFF_KH    + 8388608ull)
#define OFF_VH    (OFF_KL    + 8388608ull)               // bf16 [32][64][2048]
#define OFF_VL    (OFF_VH    + 8388608ull)
#define POOL_SZ   (OFF_VL    + 8388608ull)

__device__ __align__(1024) unsigned char g_pool[POOL_SZ];

// ---------------------------------------------------------------------------
// helpers
// ---------------------------------------------------------------------------
#define MMA16816(d, a, b) \
    asm volatile( \
        "mma.sync.aligned.m16n8k16.row.col.f32.bf16.bf16.f32 " \
        "{%0,%1,%2,%3}, {%4,%5,%6,%7}, {%8,%9}, {%0,%1,%2,%3};" \
        : "+f"((d)[0]), "+f"((d)[1]), "+f"((d)[2]), "+f"((d)[3]) \
        : "r"((a)[0]), "r"((a)[1]), "r"((a)[2]), "r"((a)[3]), \
          "r"((b)[0]), "r"((b)[1]))

#define LDSM4(r0, r1, r2, r3, a) \
    asm volatile("ldmatrix.sync.aligned.m8n8.x4.shared.b16 {%0,%1,%2,%3}, [%4];" \
        : "=r"(r0), "=r"(r1), "=r"(r2), "=r"(r3) : "r"(a))

#define CP_ASYNC16(dst, src) \
    asm volatile("cp.async.cg.shared.global [%0], [%1], 16;" \
                 :: "r"(dst), "l"(src) : "memory")
#define CP_COMMIT() asm volatile("cp.async.commit_group;" ::: "memory")

__device__ __forceinline__ uint32_t smem_u32(const void* p) {
    uint32_t a;
    asm("{ .reg .u64 t; cvta.to.shared.u64 t, %1; cvt.u32.u64 %0, t; }"
        : "=r"(a) : "l"(p));
    return a;
}

__device__ __forceinline__ uint32_t pack_bf2(float x, float y) {
    __nv_bfloat162 v = __floats2bfloat162_rn(x, y);
    return *(uint32_t*)&v;
}

// ---------------------------------------------------------------------------
// Split fp32 -> bf16 hi/lo
// ---------------------------------------------------------------------------
__global__ __launch_bounds__(256) void split_kernel(
    const float* __restrict__ in, __nv_bfloat16* __restrict__ h,
    __nv_bfloat16* __restrict__ l, int n)
{
    int i = blockIdx.x * 256 + threadIdx.x;
    if (i < n) {
        float v = in[i];
        __nv_bfloat16 hv = __float2bfloat16(v);
        h[i] = hv;
        l[i] = __float2bfloat16(v - __bfloat162float(hv));
    }
}

// ---------------------------------------------------------------------------
// Transpose + split: W[K][N] fp32 -> Th, Tl [N][K] bf16
// ---------------------------------------------------------------------------
__global__ __launch_bounds__(256) void transpose_split_kernel(
    const float* __restrict__ W, __nv_bfloat16* __restrict__ Th,
    __nv_bfloat16* __restrict__ Tl, int K, int N)
{
    __shared__ float t[32][33];
    int n0 = blockIdx.x * 32, k0 = blockIdx.y * 32;
    int tx = threadIdx.x & 31, ty = threadIdx.x >> 5;
    #pragma unroll
    for (int r = 0; r < 4; r++)
        t[ty + 8 * r][tx] = W[(size_t)(k0 + ty + 8 * r) * N + n0 + tx];
    __syncthreads();
    #pragma unroll
    for (int r = 0; r < 4; r++) {
        float v = t[tx][ty + 8 * r];
        __nv_bfloat16 hv = __float2bfloat16(v);
        size_t o = (size_t)(n0 + ty + 8 * r) * K + k0 + tx;
        Th[o] = hv;
        Tl[o] = __float2bfloat16(v - __bfloat162float(hv));
    }
}

// ---------------------------------------------------------------------------
// bf16x3 GEMM, fragment loads via ldmatrix.
// 128x128 CTA tile, 8 warps (2x4), 64x32 per warp, BK=32, double buffer.
// SMEM rows padded to 40 bf16 (80 B) -> conflict-free LDSM.
// ---------------------------------------------------------------------------
#define GSTRIDE  80u
#define GMATB    10240u
#define GSTAGE   40960u
#define GEMM_SMEM (2 * GSTAGE)
#define NCHUNK   32

__global__ __launch_bounds__(256) void gemm_bf16x3_kernel(int N,
    const __nv_bfloat16* __restrict__ Ah, const __nv_bfloat16* __restrict__ Al,
    const __nv_bfloat16* __restrict__ Bh, const __nv_bfloat16* __restrict__ Bl,
    const float* __restrict__ bias, float* __restrict__ C)
{
    extern __shared__ unsigned char smem[];
    const uint32_t sb = smem_u32(smem);

    const int tid  = threadIdx.x;
    const int lane = tid & 31;
    const int warp = tid >> 5;
    const int wm   = warp >> 2;
    const int wn   = warp & 3;
    const int g    = lane >> 2;
    const int t    = lane & 3;
    const int brow = blockIdx.y * 128;
    const int bcol = blockIdx.x * 128;

    // ldmatrix per-lane offsets (within a tile, bytes)
    const uint32_t a_lane = (uint32_t)((lane & 7) + ((lane >> 3) & 1) * 8) * GSTRIDE
                          + (uint32_t)(lane >> 4) * 16u;
    const uint32_t b_lane = (uint32_t)((lane & 7) + ((lane >> 4) & 1) * 8) * GSTRIDE
                          + (uint32_t)((lane >> 3) & 1) * 16u;

    float acc[4][4][4];
    #pragma unroll
    for (int i = 0; i < 4; i++)
        #pragma unroll
        for (int j = 0; j < 4; j++)
            #pragma unroll
            for (int r = 0; r < 4; r++) acc[i][j][r] = 0.f;

    auto load_chunk = [&](int c) {
        const uint32_t base = sb + (uint32_t)(c & 1) * GSTAGE;
        const int kc = c * 32;
        #pragma unroll
        for (int m = 0; m < 4; m++) {
            const __nv_bfloat16* src = (m == 0) ? Ah : (m == 1) ? Al
                                     : (m == 2) ? Bh : Bl;
            const int rb = (m < 2) ? brow : bcol;
            #pragma unroll
            for (int i = 0; i < 2; i++) {
                int u   = tid + i * 256;
                int row = u >> 2, q = u & 3;
                const __nv_bfloat16* gsrc =
                    src + (size_t)(rb + row) * Kn + kc + q * 8;
                uint32_t dst = base + m * GMATB + row * GSTRIDE + q * 16u;
                CP_ASYNC16(dst, gsrc);
            }
        }
        CP_COMMIT();
    };

    load_chunk(0);
    load_chunk(1);

    for (int c = 0; c < NCHUNK; c++) {
        if (c < NCHUNK - 1)
            asm volatile("cp.async.wait_group 1;" ::: "memory");
        else
            asm volatile("cp.async.wait_group 0;" ::: "memory");
        __syncthreads();

        const uint32_t stg = sb + (uint32_t)(c & 1) * GSTAGE;

        #pragma unroll
        for (int s = 0; s < 2; s++) {
            const uint32_t kb = s * 32u;
            uint32_t ah[4][4], al[4][4];
            #pragma unroll
            for (int i = 0; i < 4; i++) {
                uint32_t r = stg + (uint32_t)(wm * 64 + i * 16) * GSTRIDE + kb + a_lane;
                LDSM4(ah[i][0], ah[i][1], ah[i][2], ah[i][3], r);
                LDSM4(al[i][0], al[i][1], al[i][2], al[i][3], r + GMATB);
            }
            #pragma unroll
            for (int p = 0; p < 2; p++) {
                uint32_t bh[2][2], bl[2][2];
                uint32_t r = stg + 2u * GMATB
                           + (uint32_t)(wn * 32 + p * 16) * GSTRIDE + kb + b_lane;
                LDSM4(bh[0][0], bh[0][1], bh[1][0], bh[1][1], r);
                LDSM4(bl[0][0], bl[0][1], bl[1][0], bl[1][1], r + GMATB);
                #pragma unroll
                for (int jj = 0; jj < 2; jj++) {
                    const int j = p * 2 + jj;
                    #pragma unroll
                    for (int i = 0; i < 4; i++) {
                        MMA16816(acc[i][j], ah[i], bh[jj]);
                        MMA16816(acc[i][j], ah[i], bl[jj]);
                        MMA16816(acc[i][j], al[i], bh[jj]);
                    }
                }
            }
        }
        __syncthreads();
        if (c + 2 < NCHUNK) load_chunk(c + 2);
    }

    #pragma unroll
    for (int i = 0; i < 4; i++) {
        const int r0 = brow + wm * 64 + i * 16 + g;
        #pragma unroll
        for (int j = 0; j < 4; j++) {
            const int col = bcol + wn * 32 + j * 8 + t * 2;
            float2 bs = *(const float2*)(bias + col);
            float2 o0, o1;
            o0.x = acc[i][j][0] + bs.x;
            o0.y = acc[i][j][1] + bs.y;
            o1.x = acc[i][j][2] + bs.x;
            o1.y = acc[i][j][3] + bs.y;
            *(float2*)(C + (size_t)r0 * N + col)       = o0;
            *(float2*)(C + (size_t)(r0 + 8) * N + col) = o1;
        }
    }
}

// ---------------------------------------------------------------------------
// Prep A: RoPE + scale(Q) + hi/lo split of Q,K -> [bh][T][64] bf16
// ---------------------------------------------------------------------------
__global__ __launch_bounds__(256) void rope_split_qk_kernel(
    const float* __restrict__ qkv,
    const float* __restrict__ fcos, const float* __restrict__ fsin,
    __nv_bfloat16* __restrict__ Qh, __nv_bfloat16* __restrict__ Ql,
    __nv_bfloat16* __restrict__ Kh, __nv_bfloat16* __restrict__ Kl)
{
    int i = blockIdx.x * 256 + threadIdx.x;
    int d  = i & 31;
    int h  = (i >> 5) & 15;
    int tt = (i >> 9) & 2047;
    int b  = i >> 20;

    float c = fcos[tt * HD2n + d];
    float s = fsin[tt * HD2n + d];

    const float* qp = qkv + ((size_t)(b * Tn + tt)) * N3n + h * HDn + d;
    float q1 = qp[0],    q2 = qp[HD2n];
    float k1 = qp[Cn],   k2 = qp[Cn + HD2n];

    float rq1 = (q1 * c - q2 * s) * 0.125f;
    float rq2 = (q1 * s + q2 * c) * 0.125f;
    float rk1 = k1 * c - k2 * s;
    float rk2 = k1 * s + k2 * c;

    size_t o = ((size_t)(b * Hn + h) * Tn + tt) * HDn + d;
    __nv_bfloat16 v;
    v = __float2bfloat16(rq1); Qh[o] = v;
    Ql[o] = __float2bfloat16(rq1 - __bfloat162float(v));
    v = __float2bfloat16(rq2); Qh[o + HD2n] = v;
    Ql[o + HD2n] = __float2bfloat16(rq2 - __bfloat162float(v));
    v = __float2bfloat16(rk1); Kh[o] = v;
    Kl[o] = __float2bfloat16(rk1 - __bfloat162float(v));
    v = __float2bfloat16(rk2); Kh[o + HD2n] = v;
    Kl[o + HD2n] = __float2bfloat16(rk2 - __bfloat162float(v));
}

// ---------------------------------------------------------------------------
// Prep B: V hi/lo split + transpose -> [bh][64 hd][2048 T] bf16
// ---------------------------------------------------------------------------
__global__ __launch_bounds__(256) void v_split_t_kernel(
    const float* __restrict__ qkv,
    __nv_bfloat16* __restrict__ Vh, __nv_bfloat16* __restrict__ Vl)
{
    __shared__ float vs[64][65];
    int tb = blockIdx.x, h = blockIdx.y, b = blockIdx.z;
    int tid = threadIdx.x;
    int r = tid >> 2, cq = (tid & 3) * 16;
    const float* src = qkv + ((size_t)(b * Tn + tb * 64 + r)) * N3n
                       + 2 * Cn + h * HDn + cq;
    #pragma unroll
    for (int i = 0; i < 4; i++) {
        float4 v4 = *(const float4*)(src + i * 4);
        vs[r][cq + i * 4 + 0] = v4.x;
        vs[r][cq + i * 4 + 1] = v4.y;
        vs[r][cq + i * 4 + 2] = v4.z;
        vs[r][cq + i * 4 + 3] = v4.w;
    }
    __syncthreads();
    size_t base = ((size_t)(b * Hn + h) * HDn + r) * Tn + tb * 64 + cq;
    #pragma unroll
    for (int i = 0; i < 16; i++) {
        float v = vs[cq + i][r];
        __nv_bfloat16 hv = __float2bfloat16(v);
        Vh[base + i] = hv;
        Vl[base + i] = __float2bfloat16(v - __bfloat162float(hv));
    }
}

// ---------------------------------------------------------------------------
// Flash attention via mma.sync bf16x3, ldmatrix fragment loads.
// ---------------------------------------------------------------------------
#define FSTR      144u                 // 72 bf16 per row
#define FQ_BYTES  (128u * FSTR)        // 18432
#define FK_BYTES  (64u * FSTR)         // 9216
#define FSTAGE    (4u * FK_BYTES)      // 36864
#define FA2_SMEM  (2u * FQ_BYTES + 2u * FSTAGE)   // 110592

__global__ __launch_bounds__(256) void flash_mma_kernel(
    const __nv_bfloat16* __restrict__ Qh_, const __nv_bfloat16* __restrict__ Ql_,
    const __nv_bfloat16* __restrict__ Kh_, const __nv_bfloat16* __restrict__ Kl_,
    const __nv_bfloat16* __restrict__ Vh_, const __nv_bfloat16* __restrict__ Vl_,
    __nv_bfloat16* __restrict__ ah, __nv_bfloat16* __restrict__ al)
{
    extern __shared__ unsigned char smem[];
    const uint32_t sb = smem_u32(smem);

    const int tid  = threadIdx.x;
    const int lane = tid & 31;
    const int w    = tid >> 5;
    const int g    = lane >> 2;
    const int t    = lane & 3;

    const int qb = 15 - blockIdx.x;
    const int h  = blockIdx.y;
    const int b  = blockIdx.z;
    const int bh_ = b * Hn + h;
    const size_t qk_base = (size_t)bh_ * Tn * HDn;
    const size_t v_base  = (size_t)bh_ * HDn * Tn;
    const float L2E = 1.44269504088896f;

    // ldmatrix per-lane offsets
    const uint32_t a_lane = (uint32_t)((lane & 7) + ((lane >> 3) & 1) * 8) * FSTR
                          + (uint32_t)(lane >> 4) * 16u;
    const uint32_t b_lane = (uint32_t)((lane & 7) + ((lane >> 4) & 1) * 8) * FSTR
                          + (uint32_t)((lane >> 3) & 1) * 16u;

    // Q tiles (group 0)
    #pragma unroll
    for (int i = 0; i < 4; i++) {
        int u = tid + i * 256;
        int row = u >> 3, q = u & 7;
        size_t gof = qk_base + (size_t)(qb * 128 + row) * HDn + q * 8;
        CP_ASYNC16(sb + row * FSTR + q * 16u, Qh_ + gof);
        CP_ASYNC16(sb + FQ_BYTES + row * FSTR + q * 16u, Ql_ + gof);
    }
    CP_COMMIT();

    auto load_kv = [&](int kb) {
        uint32_t base = sb + 2u * FQ_BYTES + (uint32_t)(kb & 1) * FSTAGE;
        #pragma unroll
        for (int i = 0; i < 2; i++) {
            int u = tid + i * 256;
            int row = u >> 3, q = u & 7;
            size_t kof = qk_base + (size_t)(kb * 64 + row) * HDn + q * 8;
            size_t vof = v_base + (size_t)row * Tn + kb * 64 + q * 8;
            CP_ASYNC16(base + row * FSTR + q * 16u, Kh_ + kof);
            CP_ASYNC16(base + FK_BYTES + row * FSTR + q * 16u, Kl_ + kof);
            CP_ASYNC16(base + 2u * FK_BYTES + row * FSTR + q * 16u, Vh_ + vof);
            CP_ASYNC16(base + 3u * FK_BYTES + row * FSTR + q * 16u, Vl_ + vof);
        }
        CP_COMMIT();
    };

    float o[8][4];
    #pragma unroll
    for (int j = 0; j < 8; j++)
        #pragma unroll
        for (int e = 0; e < 4; e++) o[j][e] = 0.f;
    float m_i[2] = {-1e30f, -1e30f};
    float l_i[2] = {0.f, 0.f};

    const int row_hi = qb * 128 + w * 16 + 15;
    const int nkb = 2 * qb + 2;

    load_kv(0);

    for (int kb = 0; kb < nkb; kb++) {
        if (kb + 1 < nkb) {
            load_kv(kb + 1);
            asm volatile("cp.async.wait_group 1;" ::: "memory");
        } else {
            asm volatile("cp.async.wait_group 0;" ::: "memory");
        }
        __syncthreads();

        const bool active = (kb * 64 <= row_hi);
        if (active) {
            const uint32_t kbase = sb + 2u * FQ_BYTES + (uint32_t)(kb & 1) * FSTAGE;

            // ---- S = Q K^T (3 terms) ----
            float s[8][4];
            #pragma unroll
            for (int j = 0; j < 8; j++)
                #pragma unroll
                for (int e = 0; e < 4; e++) s[j][e] = 0.f;

            #pragma unroll
            for (int kk = 0; kk < 4; kk++) {
                uint32_t qaddr = sb + (uint32_t)(w * 16) * FSTR + 32u * kk + a_lane;
                uint32_t aQh[4], aQl[4];
                LDSM4(aQh[0], aQh[1], aQh[2], aQh[3], qaddr);
                LDSM4(aQl[0], aQl[1], aQl[2], aQl[3], qaddr + FQ_BYTES);
                #pragma unroll
                for (int p = 0; p < 4; p++) {
                    uint32_t bKh[2][2], bKl[2][2];
                    uint32_t br = kbase + (uint32_t)(p * 16) * FSTR + 32u * kk + b_lane;
                    LDSM4(bKh[0][0], bKh[0][1], bKh[1][0], bKh[1][1], br);
                    LDSM4(bKl[0][0], bKl[0][1], bKl[1][0], bKl[1][1], br + FK_BYTES);
                    #pragma unroll
                    for (int jj = 0; jj < 2; jj++) {
                        const int j = p * 2 + jj;
                        MMA16816(s[j], aQh, bKh[jj]);
                        MMA16816(s[j], aQh, bKl[jj]);
                        MMA16816(s[j], aQl, bKh[jj]);
                    }
                }
            }

            // ---- causal mask ----
            if (kb * 64 + 63 > qb * 128 + w * 16) {
                #pragma unroll
                for (int j = 0; j < 8; j++)
                    #pragma unroll
                    for (int e = 0; e < 4; e++) {
                        int col = kb * 64 + j * 8 + 2 * t + (e & 1);
                        int row = qb * 128 + w * 16 + g + ((e >> 1) << 3);
                        if (col > row) s[j][e] = -1e30f;
                    }
            }

            // ---- online softmax ----
            #pragma unroll
            for (int u = 0; u < 2; u++) {
                float mx = -1e30f;
                #pragma unroll
                for (int j = 0; j < 8; j++)
                    mx = fmaxf(mx, fmaxf(s[j][2 * u], s[j][2 * u + 1]));
                mx = fmaxf(mx, __shfl_xor_sync(0xffffffffu, mx, 1));
                mx = fmaxf(mx, __shfl_xor_sync(0xffffffffu, mx, 2));
                float mnew  = fmaxf(m_i[u], mx);
                float alpha = exp2f((m_i[u] - mnew) * L2E);
                m_i[u] = mnew;
                float rs = 0.f;
                #pragma unroll
                for (int j = 0; j < 8; j++) {
                    float p0 = exp2f((s[j][2 * u]     - mnew) * L2E);
                    float p1 = exp2f((s[j][2 * u + 1] - mnew) * L2E);
                    s[j][2 * u] = p0; s[j][2 * u + 1] = p1;
                    rs += p0 + p1;
                }
                rs += __shfl_xor_sync(0xffffffffu, rs, 1);
                rs += __shfl_xor_sync(0xffffffffu, rs, 2);
                l_i[u] = l_i[u] * alpha + rs;
                #pragma unroll
                for (int j = 0; j < 8; j++) {
                    o[j][2 * u]     *= alpha;
                    o[j][2 * u + 1] *= alpha;
                }
            }

            // ---- O += P V (3 terms) ----
            const uint32_t vbase = kbase + 2u * FK_BYTES;
            #pragma unroll
            for (int kk = 0; kk < 4; kk++) {
                const int n0 = 2 * kk, n1 = 2 * kk + 1;
                uint32_t aPh[4], aPl[4];
                {
                    float p00 = s[n0][0], p01 = s[n0][1];
                    float p02 = s[n0][2], p03 = s[n0][3];
                    float p10 = s[n1][0], p11 = s[n1][1];
                    float p12 = s[n1][2], p13 = s[n1][3];
                    __nv_bfloat16 h00 = __float2bfloat16(p00);
                    __nv_bfloat16 h01 = __float2bfloat16(p01);
                    __nv_bfloat16 h02 = __float2bfloat16(p02);
                    __nv_bfloat16 h03 = __float2bfloat16(p03);
                    __nv_bfloat16 h10 = __float2bfloat16(p10);
                    __nv_bfloat16 h11 = __float2bfloat16(p11);
                    __nv_bfloat16 h12 = __float2bfloat16(p12);
                    __nv_bfloat16 h13 = __float2bfloat16(p13);
                    aPh[0] = ((uint32_t)*(uint16_t*)&h01 << 16) | *(uint16_t*)&h00;
                    aPh[1] = ((uint32_t)*(uint16_t*)&h03 << 16) | *(uint16_t*)&h02;
                    aPh[2] = ((uint32_t)*(uint16_t*)&h11 << 16) | *(uint16_t*)&h10;
                    aPh[3] = ((uint32_t)*(uint16_t*)&h13 << 16) | *(uint16_t*)&h12;
                    aPl[0] = pack_bf2(p00 - __bfloat162float(h00),
                                      p01 - __bfloat162float(h01));
                    aPl[1] = pack_bf2(p02 - __bfloat162float(h02),
                                      p03 - __bfloat162float(h03));
                    aPl[2] = pack_bf2(p10 - __bfloat162float(h10),
                                      p11 - __bfloat162float(h11));
                    aPl[3] = pack_bf2(p12 - __bfloat162float(h12),
                                      p13 - __bfloat162float(h13));
                }
                #pragma unroll
                for (int p = 0; p < 4; p++) {
                    uint32_t bVh[2][2], bVl[2][2];
                    uint32_t br = vbase + (uint32_t)(p * 16) * FSTR + 32u * kk + b_lane;
                    LDSM4(bVh[0][0], bVh[0][1], bVh[1][0], bVh[1][1], br);
                    LDSM4(bVl[0][0], bVl[0][1], bVl[1][0], bVl[1][1], br + FK_BYTES);
                    #pragma unroll
                    for (int jj = 0; jj < 2; jj++) {
                        const int j = p * 2 + jj;
                        MMA16816(o[j], aPh, bVh[jj]);
                        MMA16816(o[j], aPl, bVh[jj]);
                        MMA16816(o[j], aPh, bVl[jj]);
                    }
                }
            }
        }
        __syncthreads();
    }

    // ---- epilogue ----
    #pragma unroll
    for (int u = 0; u < 2; u++) {
        float inv = 1.0f / l_i[u];
        int row = b * Tn + qb * 128 + w * 16 + u * 8 + g;
        #pragma unroll
        for (int j = 0; j < 8; j++) {
            float p0 = o[j][2 * u] * inv;
            float p1 = o[j][2 * u + 1] * inv;
            __nv_bfloat16 h0 = __float2bfloat16(p0);
            __nv_bfloat16 h1 = __float2bfloat16(p1);
            uint32_t hi = ((uint32_t)*(uint16_t*)&h1 << 16) | *(uint16_t*)&h0;
            uint32_t lo = pack_bf2(p0 - __bfloat162float(h0),
                                   p1 - __bfloat162float(h1));
            size_t off = (size_t)row * Cn + h * HDn + j * 8 + 2 * t;
            *(uint32_t*)(ah + off) = hi;
            *(uint32_t*)(al + off) = lo;
        }
    }
}

// ---------------------------------------------------------------------------
extern "C" void kernel_launch(void* const* d_in, const int* in_sizes, int n_in,
                              void* d_out, int out_size)
{
    const float* x     = (const float*)d_in[0];
    const float* fcos  = (const float*)d_in[1];
    const float* fsin  = (const float*)d_in[2];
    const float* Wqkv  = (const float*)d_in[3];
    const float* bqkv  = (const float*)d_in[4];
    const float* Wproj = (const float*)d_in[5];
    const float* bproj = (const float*)d_in[6];
    float* out = (float*)d_out;

    unsigned char* pool = nullptr;
    cudaGetSymbolAddress((void**)&pool, g_pool);
    float* qkv = (float*)(pool + OFF_QKV);
    __nv_bfloat16* xh  = (__nv_bfloat16*)(pool + OFF_XH);
    __nv_bfloat16* xl  = (__nv_bfloat16*)(pool + OFF_XL);
    __nv_bfloat16* wqh = (__nv_bfloat16*)(pool + OFF_WQH);
    __nv_bfloat16* wql = (__nv_bfloat16*)(pool + OFF_WQL);
    __nv_bfloat16* wph = (__nv_bfloat16*)(pool + OFF_WPH);
    __nv_bfloat16* wpl = (__nv_bfloat16*)(pool + OFF_WPL);
    __nv_bfloat16* ah  = (__nv_bfloat16*)(pool + OFF_AH);
    __nv_bfloat16* al  = (__nv_bfloat16*)(pool + OFF_AL);
    __nv_bfloat16* qh  = (__nv_bfloat16*)(pool + OFF_QH);
    __nv_bfloat16* ql  = (__nv_bfloat16*)(pool + OFF_QL);
    __nv_bfloat16* kh  = (__nv_bfloat16*)(pool + OFF_KH);
    __nv_bfloat16* kl  = (__nv_bfloat16*)(pool + OFF_KL);
    __nv_bfloat16* vh  = (__nv_bfloat16*)(pool + OFF_VH);
    __nv_bfloat16* vl  = (__nv_bfloat16*)(pool + OFF_VL);

    cudaFuncSetAttribute(gemm_bf16x3_kernel,
                         cudaFuncAttributeMaxDynamicSharedMemorySize, GEMM_SMEM);
    cudaFuncSetAttribute(flash_mma_kernel,
                         cudaFuncAttributeMaxDynamicSharedMemorySize, FA2_SMEM);

    // prep
    split_kernel<<<(Mn * Cn) / 256, 256>>>(x, xh, xl, Mn * Cn);
    transpose_split_kernel<<<dim3(N3n / 32, Kn / 32), 256>>>(Wqkv, wqh, wql, Kn, N3n);
    transpose_split_kernel<<<dim3(Cn / 32, Kn / 32), 256>>>(Wproj, wph, wpl, Kn, Cn);

    // 1) qkv = x @ Wqkv + bqkv
    gemm_bf16x3_kernel<<<dim3(N3n / 128, Mn / 128), 256, GEMM_SMEM>>>(
        N3n, xh, xl, wqh, wql, bqkv, qkv);

    // 2) RoPE + split Q,K ; split+transpose V
    rope_split_qk_kernel<<<(Bn * Tn * Hn * 32) / 256, 256>>>(
        qkv, fcos, fsin, qh, ql, kh, kl);
    v_split_t_kernel<<<dim3(Tn / 64, Hn, Bn), 256>>>(qkv, vh, vl);

    // 3) flash attention (mma) -> ah/al bf16 hi/lo
    flash_mma_kernel<<<dim3(Tn / 128, Hn, Bn), 256, FA2_SMEM>>>(
        qh, ql, kh, kl, vh, vl, ah, al);

    // 4) out = att @ Wproj + bproj
    gemm_bf16x3_kernel<<<dim3(Cn / 128, Mn / 128), 256, GEMM_SMEM>>>(
        Cn, ah, al, wph, wpl, bproj, out);
}

// round 9
// speedup vs baseline: 2.4139x; 1.0136x over previous
#include <cuda_runtime.h>
#include <cuda_bf16.h>
#include <cstdint>
#include <math.h>

#define Bn   2
#define Tn   2048
#define Cn   1024
#define Hn   16
#define HDn  64
#define HD2n 32
#define Mn   (Bn * Tn)          // 4096
#define N3n  (3 * Cn)           // 3072
#define Kn   1024

// ---------------------------------------------------------------------------
// Scratch pool
// ---------------------------------------------------------------------------
#define OFF_QKV   0ull                                   // fp32 [4096][3072]
#define OFF_XH    (OFF_QKV   + 50331648ull)              // bf16 [4096][1024]
#define OFF_XL    (OFF_XH    + 8388608ull)
#define OFF_WQH   (OFF_XL    + 8388608ull)               // bf16 [3072][1024]
#define OFF_WQL   (OFF_WQH   + 6291456ull)
#define OFF_WPH   (OFF_WQL   + 6291456ull)               // bf16 [1024][1024]
#define OFF_WPL   (OFF_WPH   + 2097152ull)
#define OFF_AH    (OFF_WPL   + 2097152ull)               // bf16 [4096][1024]
#define OFF_AL    (OFF_AH    + 8388608ull)
#define OFF_QH    (OFF_AL    + 8388608ull)               // bf16 [32][2048][64]
#define OFF_QL    (OFF_QH    + 8388608ull)
#define OFF_KH    (OFF_QL    + 8388608ull)
#define OFF_KL    (OFF_KH    + 8388608ull)
#define OFF_VH    (OFF_KL    + 8388608ull)               // bf16 [32][64][2048]
#define OFF_VL    (OFF_VH    + 8388608ull)
#define POOL_SZ   (OFF_VL    + 8388608ull)

__device__ __align__(1024) unsigned char g_pool[POOL_SZ];

// ---------------------------------------------------------------------------
// helpers
// ---------------------------------------------------------------------------
#define MMA16816(d, a, b) \
    asm volatile( \
        "mma.sync.aligned.m16n8k16.row.col.f32.bf16.bf16.f32 " \
        "{%0,%1,%2,%3}, {%4,%5,%6,%7}, {%8,%9}, {%0,%1,%2,%3};" \
        : "+f"((d)[0]), "+f"((d)[1]), "+f"((d)[2]), "+f"((d)[3]) \
        : "r"((a)[0]), "r"((a)[1]), "r"((a)[2]), "r"((a)[3]), \
          "r"((b)[0]), "r"((b)[1]))

#define LDSM4(r0, r1, r2, r3, a) \
    asm volatile("ldmatrix.sync.aligned.m8n8.x4.shared.b16 {%0,%1,%2,%3}, [%4];" \
        : "=r"(r0), "=r"(r1), "=r"(r2), "=r"(r3) : "r"(a))

#define CP_ASYNC16(dst, src) \
    asm volatile("cp.async.cg.shared.global [%0], [%1], 16;" \
                 :: "r"(dst), "l"(src) : "memory")
#define CP_COMMIT() asm volatile("cp.async.commit_group;" ::: "memory")

__device__ __forceinline__ uint32_t smem_u32(const void* p) {
    uint32_t a;
    asm("{ .reg .u64 t; cvta.to.shared.u64 t, %1; cvt.u32.u64 %0, t; }"
        : "=r"(a) : "l"(p));
    return a;
}

__device__ __forceinline__ uint32_t pack_bf2(float x, float y) {
    __nv_bfloat162 v = __floats2bfloat162_rn(x, y);
    return *(uint32_t*)&v;
}

// ---------------------------------------------------------------------------
// Split fp32 -> bf16 hi/lo
// ---------------------------------------------------------------------------
__global__ __launch_bounds__(256) void split_kernel(
    const float* __restrict__ in, __nv_bfloat16* __restrict__ h,
    __nv_bfloat16* __restrict__ l, int n)
{
    int i = blockIdx.x * 256 + threadIdx.x;
    if (i < n) {
        float v = in[i];
        __nv_bfloat16 hv = __float2bfloat16(v);
        h[i] = hv;
        l[i] = __float2bfloat16(v - __bfloat162float(hv));
    }
}

// ---------------------------------------------------------------------------
// Transpose + split: W[K][N] fp32 -> Th, Tl [N][K] bf16
// ---------------------------------------------------------------------------
__global__ __launch_bounds__(256) void transpose_split_kernel(
    const float* __restrict__ W, __nv_bfloat16* __restrict__ Th,
    __nv_bfloat16* __restrict__ Tl, int K, int N)
{
    __shared__ float t[32][33];
    int n0 = blockIdx.x * 32, k0 = blockIdx.y * 32;
    int tx = threadIdx.x & 31, ty = threadIdx.x >> 5;
    #pragma unroll
    for (int r = 0; r < 4; r++)
        t[ty + 8 * r][tx] = W[(size_t)(k0 + ty + 8 * r) * N + n0 + tx];
    __syncthreads();
    #pragma unroll
    for (int r = 0; r < 4; r++) {
        float v = t[tx][ty + 8 * r];
        __nv_bfloat16 hv = __float2bfloat16(v);
        size_t o = (size_t)(n0 + ty + 8 * r) * K + k0 + tx;
        Th[o] = hv;
        Tl[o] = __float2bfloat16(v - __bfloat162float(hv));
    }
}

// ---------------------------------------------------------------------------
// bf16x3 GEMM, ldmatrix loads, 2 CTAs/SM target.
// 128x128 CTA tile, 8 warps (2x4), 64x32 per warp, BK=32, double buffer.
// ---------------------------------------------------------------------------
#define GSTRIDE  80u
#define GMATB    10240u
#define GSTAGE   40960u
#define GEMM_SMEM (2 * GSTAGE)
#define NCHUNK   32

__global__ __launch_bounds__(256, 2) void gemm_bf16x3_kernel(int N,
    const __nv_bfloat16* __restrict__ Ah, const __nv_bfloat16* __restrict__ Al,
    const __nv_bfloat16* __restrict__ Bh, const __nv_bfloat16* __restrict__ Bl,
    const float* __restrict__ bias, float* __restrict__ C)
{
    extern __shared__ unsigned char smem[];
    const uint32_t sb = smem_u32(smem);

    const int tid  = threadIdx.x;
    const int lane = tid & 31;
    const int warp = tid >> 5;
    const int wm   = warp >> 2;
    const int wn   = warp & 3;
    const int g    = lane >> 2;
    const int t    = lane & 3;
    const int brow = blockIdx.y * 128;
    const int bcol = blockIdx.x * 128;

    const uint32_t a_lane = (uint32_t)((lane & 7) + ((lane >> 3) & 1) * 8) * GSTRIDE
                          + (uint32_t)(lane >> 4) * 16u;
    const uint32_t b_lane = (uint32_t)((lane & 7) + ((lane >> 4) & 1) * 8) * GSTRIDE
                          + (uint32_t)((lane >> 3) & 1) * 16u;

    float acc[4][4][4];
    #pragma unroll
    for (int i = 0; i < 4; i++)
        #pragma unroll
        for (int j = 0; j < 4; j++)
            #pragma unroll
            for (int r = 0; r < 4; r++) acc[i][j][r] = 0.f;

    auto load_chunk = [&](int c) {
        const uint32_t base = sb + (uint32_t)(c & 1) * GSTAGE;
        const int kc = c * 32;
        #pragma unroll
        for (int m = 0; m < 4; m++) {
            const __nv_bfloat16* src = (m == 0) ? Ah : (m == 1) ? Al
                                     : (m == 2) ? Bh : Bl;
            const int rb = (m < 2) ? brow : bcol;
            #pragma unroll
            for (int i = 0; i < 2; i++) {
                int u   = tid + i * 256;
                int row = u >> 2, q = u & 3;
                const __nv_bfloat16* gsrc =
                    src + (size_t)(rb + row) * Kn + kc + q * 8;
                uint32_t dst = base + m * GMATB + row * GSTRIDE + q * 16u;
                CP_ASYNC16(dst, gsrc);
            }
        }
        CP_COMMIT();
    };

    load_chunk(0);
    load_chunk(1);

    for (int c = 0; c < NCHUNK; c++) {
        if (c < NCHUNK - 1)
            asm volatile("cp.async.wait_group 1;" ::: "memory");
        else
            asm volatile("cp.async.wait_group 0;" ::: "memory");
        __syncthreads();

        const uint32_t stg = sb + (uint32_t)(c & 1) * GSTAGE;

        #pragma unroll
        for (int s = 0; s < 2; s++) {
            const uint32_t kb = s * 32u;
            uint32_t ah[4][4], al[4][4];
            #pragma unroll
            for (int i = 0; i < 4; i++) {
                uint32_t r = stg + (uint32_t)(wm * 64 + i * 16) * GSTRIDE + kb + a_lane;
                LDSM4(ah[i][0], ah[i][1], ah[i][2], ah[i][3], r);
                LDSM4(al[i][0], al[i][1], al[i][2], al[i][3], r + GMATB);
            }
            #pragma unroll
            for (int p = 0; p < 2; p++) {
                uint32_t bh[2][2], bl[2][2];
                uint32_t r = stg + 2u * GMATB
                           + (uint32_t)(wn * 32 + p * 16) * GSTRIDE + kb + b_lane;
                LDSM4(bh[0][0], bh[0][1], bh[1][0], bh[1][1], r);
                LDSM4(bl[0][0], bl[0][1], bl[1][0], bl[1][1], r + GMATB);
                // term-major emission: same-acc MMAs separated by 4 indep MMAs
                #pragma unroll
                for (int jj = 0; jj < 2; jj++) {
                    const int j = p * 2 + jj;
                    #pragma unroll
                    for (int i = 0; i < 4; i++) MMA16816(acc[i][j], ah[i], bh[jj]);
                    #pragma unroll
                    for (int i = 0; i < 4; i++) MMA16816(acc[i][j], ah[i], bl[jj]);
                    #pragma unroll
                    for (int i = 0; i < 4; i++) MMA16816(acc[i][j], al[i], bh[jj]);
                }
            }
        }
        __syncthreads();
        if (c + 2 < NCHUNK) load_chunk(c + 2);
    }

    #pragma unroll
    for (int i = 0; i < 4; i++) {
        const int r0 = brow + wm * 64 + i * 16 + g;
        #pragma unroll
        for (int j = 0; j < 4; j++) {
            const int col = bcol + wn * 32 + j * 8 + t * 2;
            float2 bs = *(const float2*)(bias + col);
            float2 o0, o1;
            o0.x = acc[i][j][0] + bs.x;
            o0.y = acc[i][j][1] + bs.y;
            o1.x = acc[i][j][2] + bs.x;
            o1.y = acc[i][j][3] + bs.y;
            *(float2*)(C + (size_t)r0 * N + col)       = o0;
            *(float2*)(C + (size_t)(r0 + 8) * N + col) = o1;
        }
    }
}

// ---------------------------------------------------------------------------
// Prep A: RoPE + scale(Q) + hi/lo split of Q,K -> [bh][T][64] bf16
// ---------------------------------------------------------------------------
__global__ __launch_bounds__(256) void rope_split_qk_kernel(
    const float* __restrict__ qkv,
    const float* __restrict__ fcos, const float* __restrict__ fsin,
    __nv_bfloat16* __restrict__ Qh, __nv_bfloat16* __restrict__ Ql,
    __nv_bfloat16* __restrict__ Kh, __nv_bfloat16* __restrict__ Kl)
{
    int i = blockIdx.x * 256 + threadIdx.x;
    int d  = i & 31;
    int h  = (i >> 5) & 15;
    int tt = (i >> 9) & 2047;
    int b  = i >> 20;

    float c = fcos[tt * HD2n + d];
    float s = fsin[tt * HD2n + d];

    const float* qp = qkv + ((size_t)(b * Tn + tt)) * N3n + h * HDn + d;
    float q1 = qp[0],    q2 = qp[HD2n];
    float k1 = qp[Cn],   k2 = qp[Cn + HD2n];

    float rq1 = (q1 * c - q2 * s) * 0.125f;
    float rq2 = (q1 * s + q2 * c) * 0.125f;
    float rk1 = k1 * c - k2 * s;
    float rk2 = k1 * s + k2 * c;

    size_t o = ((size_t)(b * Hn + h) * Tn + tt) * HDn + d;
    __nv_bfloat16 v;
    v = __float2bfloat16(rq1); Qh[o] = v;
    Ql[o] = __float2bfloat16(rq1 - __bfloat162float(v));
    v = __float2bfloat16(rq2); Qh[o + HD2n] = v;
    Ql[o + HD2n] = __float2bfloat16(rq2 - __bfloat162float(v));
    v = __float2bfloat16(rk1); Kh[o] = v;
    Kl[o] = __float2bfloat16(rk1 - __bfloat162float(v));
    v = __float2bfloat16(rk2); Kh[o + HD2n] = v;
    Kl[o + HD2n] = __float2bfloat16(rk2 - __bfloat162float(v));
}

// ---------------------------------------------------------------------------
// Prep B: V hi/lo split + transpose -> [bh][64 hd][2048 T] bf16
// ---------------------------------------------------------------------------
__global__ __launch_bounds__(256) void v_split_t_kernel(
    const float* __restrict__ qkv,
    __nv_bfloat16* __restrict__ Vh, __nv_bfloat16* __restrict__ Vl)
{
    __shared__ float vs[64][65];
    int tb = blockIdx.x, h = blockIdx.y, b = blockIdx.z;
    int tid = threadIdx.x;
    int r = tid >> 2, cq = (tid & 3) * 16;
    const float* src = qkv + ((size_t)(b * Tn + tb * 64 + r)) * N3n
                       + 2 * Cn + h * HDn + cq;
    #pragma unroll
    for (int i = 0; i < 4; i++) {
        float4 v4 = *(const float4*)(src + i * 4);
        vs[r][cq + i * 4 + 0] = v4.x;
        vs[r][cq + i * 4 + 1] = v4.y;
        vs[r][cq + i * 4 + 2] = v4.z;
        vs[r][cq + i * 4 + 3] = v4.w;
    }
    __syncthreads();
    size_t base = ((size_t)(b * Hn + h) * HDn + r) * Tn + tb * 64 + cq;
    #pragma unroll
    for (int i = 0; i < 16; i++) {
        float v = vs[cq + i][r];
        __nv_bfloat16 hv = __float2bfloat16(v);
        Vh[base + i] = hv;
        Vl[base + i] = __float2bfloat16(v - __bfloat162float(hv));
    }
}

// ---------------------------------------------------------------------------
// Flash attention via mma.sync bf16x3, ldmatrix fragment loads.
// ---------------------------------------------------------------------------
#define FSTR      144u                 // 72 bf16 per row
#define FQ_BYTES  (128u * FSTR)        // 18432
#define FK_BYTES  (64u * FSTR)         // 9216
#define FSTAGE    (4u * FK_BYTES)      // 36864
#define FA2_SMEM  (2u * FQ_BYTES + 2u * FSTAGE)   // 110592

__global__ __launch_bounds__(256) void flash_mma_kernel(
    const __nv_bfloat16* __restrict__ Qh_, const __nv_bfloat16* __restrict__ Ql_,
    const __nv_bfloat16* __restrict__ Kh_, const __nv_bfloat16* __restrict__ Kl_,
    const __nv_bfloat16* __restrict__ Vh_, const __nv_bfloat16* __restrict__ Vl_,
    __nv_bfloat16* __restrict__ ah, __nv_bfloat16* __restrict__ al)
{
    extern __shared__ unsigned char smem[];
    const uint32_t sb = smem_u32(smem);

    const int tid  = threadIdx.x;
    const int lane = tid & 31;
    const int w    = tid >> 5;
    const int g    = lane >> 2;
    const int t    = lane & 3;

    const int qb = 15 - blockIdx.x;
    const int h  = blockIdx.y;
    const int b  = blockIdx.z;
    const int bh_ = b * Hn + h;
    const size_t qk_base = (size_t)bh_ * Tn * HDn;
    const size_t v_base  = (size_t)bh_ * HDn * Tn;
    const float L2E = 1.44269504088896f;

    const uint32_t a_lane = (uint32_t)((lane & 7) + ((lane >> 3) & 1) * 8) * FSTR
                          + (uint32_t)(lane >> 4) * 16u;
    const uint32_t b_lane = (uint32_t)((lane & 7) + ((lane >> 4) & 1) * 8) * FSTR
                          + (uint32_t)((lane >> 3) & 1) * 16u;

    #pragma unroll
    for (int i = 0; i < 4; i++) {
        int u = tid + i * 256;
        int row = u >> 3, q = u & 7;
        size_t gof = qk_base + (size_t)(qb * 128 + row) * HDn + q * 8;
        CP_ASYNC16(sb + row * FSTR + q * 16u, Qh_ + gof);
        CP_ASYNC16(sb + FQ_BYTES + row * FSTR + q * 16u, Ql_ + gof);
    }
    CP_COMMIT();

    auto load_kv = [&](int kb) {
        uint32_t base = sb + 2u * FQ_BYTES + (uint32_t)(kb & 1) * FSTAGE;
        #pragma unroll
        for (int i = 0; i < 2; i++) {
            int u = tid + i * 256;
            int row = u >> 3, q = u & 7;
            size_t kof = qk_base + (size_t)(kb * 64 + row) * HDn + q * 8;
            size_t vof = v_base + (size_t)row * Tn + kb * 64 + q * 8;
            CP_ASYNC16(base + row * FSTR + q * 16u, Kh_ + kof);
            CP_ASYNC16(base + FK_BYTES + row * FSTR + q * 16u, Kl_ + kof);
            CP_ASYNC16(base + 2u * FK_BYTES + row * FSTR + q * 16u, Vh_ + vof);
            CP_ASYNC16(base + 3u * FK_BYTES + row * FSTR + q * 16u, Vl_ + vof);
        }
        CP_COMMIT();
    };

    float o[8][4];
    #pragma unroll
    for (int j = 0; j < 8; j++)
        #pragma unroll
        for (int e = 0; e < 4; e++) o[j][e] = 0.f;
    float m_i[2] = {-1e30f, -1e30f};
    float l_i[2] = {0.f, 0.f};

    const int row_hi = qb * 128 + w * 16 + 15;
    const int nkb = 2 * qb + 2;

    load_kv(0);

    for (int kb = 0; kb < nkb; kb++) {
        if (kb + 1 < nkb) {
            load_kv(kb + 1);
            asm volatile("cp.async.wait_group 1;" ::: "memory");
        } else {
            asm volatile("cp.async.wait_group 0;" ::: "memory");
        }
        __syncthreads();

        const bool active = (kb * 64 <= row_hi);
        if (active) {
            const uint32_t kbase = sb + 2u * FQ_BYTES + (uint32_t)(kb & 1) * FSTAGE;

            float s[8][4];
            #pragma unroll
            for (int j = 0; j < 8; j++)
                #pragma unroll
                for (int e = 0; e < 4; e++) s[j][e] = 0.f;

            #pragma unroll
            for (int kk = 0; kk < 4; kk++) {
                uint32_t qaddr = sb + (uint32_t)(w * 16) * FSTR + 32u * kk + a_lane;
                uint32_t aQh[4], aQl[4];
                LDSM4(aQh[0], aQh[1], aQh[2], aQh[3], qaddr);
                LDSM4(aQl[0], aQl[1], aQl[2], aQl[3], qaddr + FQ_BYTES);
                #pragma unroll
                for (int p = 0; p < 4; p++) {
                    uint32_t bKh[2][2], bKl[2][2];
                    uint32_t br = kbase + (uint32_t)(p * 16) * FSTR + 32u * kk + b_lane;
                    LDSM4(bKh[0][0], bKh[0][1], bKh[1][0], bKh[1][1], br);
                    LDSM4(bKl[0][0], bKl[0][1], bKl[1][0], bKl[1][1], br + FK_BYTES);
                    #pragma unroll
                    for (int jj = 0; jj < 2; jj++) {
                        const int j = p * 2 + jj;
                        MMA16816(s[j], aQh, bKh[jj]);
                        MMA16816(s[j], aQh, bKl[jj]);
                        MMA16816(s[j], aQl, bKh[jj]);
                    }
                }
            }

            if (kb * 64 + 63 > qb * 128 + w * 16) {
                #pragma unroll
                for (int j = 0; j < 8; j++)
                    #pragma unroll
                    for (int e = 0; e < 4; e++) {
                        int col = kb * 64 + j * 8 + 2 * t + (e & 1);
                        int row = qb * 128 + w * 16 + g + ((e >> 1) << 3);
                        if (col > row) s[j][e] = -1e30f;
                    }
            }

            #pragma unroll
            for (int u = 0; u < 2; u++) {
                float mx = -1e30f;
                #pragma unroll
                for (int j = 0; j < 8; j++)
                    mx = fmaxf(mx, fmaxf(s[j][2 * u], s[j][2 * u + 1]));
                mx = fmaxf(mx, __shfl_xor_sync(0xffffffffu, mx, 1));
                mx = fmaxf(mx, __shfl_xor_sync(0xffffffffu, mx, 2));
                float mnew  = fmaxf(m_i[u], mx);
                float alpha = exp2f((m_i[u] - mnew) * L2E);
                m_i[u] = mnew;
                float rs = 0.f;
                #pragma unroll
                for (int j = 0; j < 8; j++) {
                    float p0 = exp2f((s[j][2 * u]     - mnew) * L2E);
                    float p1 = exp2f((s[j][2 * u + 1] - mnew) * L2E);
                    s[j][2 * u] = p0; s[j][2 * u + 1] = p1;
                    rs += p0 + p1;
                }
                rs += __shfl_xor_sync(0xffffffffu, rs, 1);
                rs += __shfl_xor_sync(0xffffffffu, rs, 2);
                l_i[u] = l_i[u] * alpha + rs;
                #pragma unroll
                for (int j = 0; j < 8; j++) {
                    o[j][2 * u]     *= alpha;
                    o[j][2 * u + 1] *= alpha;
                }
            }

            const uint32_t vbase = kbase + 2u * FK_BYTES;
            #pragma unroll
            for (int kk = 0; kk < 4; kk++) {
                const int n0 = 2 * kk, n1 = 2 * kk + 1;
                uint32_t aPh[4], aPl[4];
                {
                    float p00 = s[n0][0], p01 = s[n0][1];
                    float p02 = s[n0][2], p03 = s[n0][3];
                    float p10 = s[n1][0], p11 = s[n1][1];
                    float p12 = s[n1][2], p13 = s[n1][3];
                    __nv_bfloat16 h00 = __float2bfloat16(p00);
                    __nv_bfloat16 h01 = __float2bfloat16(p01);
                    __nv_bfloat16 h02 = __float2bfloat16(p02);
                    __nv_bfloat16 h03 = __float2bfloat16(p03);
                    __nv_bfloat16 h10 = __float2bfloat16(p10);
                    __nv_bfloat16 h11 = __float2bfloat16(p11);
                    __nv_bfloat16 h12 = __float2bfloat16(p12);
                    __nv_bfloat16 h13 = __float2bfloat16(p13);
                    aPh[0] = ((uint32_t)*(uint16_t*)&h01 << 16) | *(uint16_t*)&h00;
                    aPh[1] = ((uint32_t)*(uint16_t*)&h03 << 16) | *(uint16_t*)&h02;
                    aPh[2] = ((uint32_t)*(uint16_t*)&h11 << 16) | *(uint16_t*)&h10;
                    aPh[3] = ((uint32_t)*(uint16_t*)&h13 << 16) | *(uint16_t*)&h12;
                    aPl[0] = pack_bf2(p00 - __bfloat162float(h00),
                                      p01 - __bfloat162float(h01));
                    aPl[1] = pack_bf2(p02 - __bfloat162float(h02),
                                      p03 - __bfloat162float(h03));
                    aPl[2] = pack_bf2(p10 - __bfloat162float(h10),
                                      p11 - __bfloat162float(h11));
                    aPl[3] = pack_bf2(p12 - __bfloat162float(h12),
                                      p13 - __bfloat162float(h13));
                }
                #pragma unroll
                for (int p = 0; p < 4; p++) {
                    uint32_t bVh[2][2], bVl[2][2];
                    uint32_t br = vbase + (uint32_t)(p * 16) * FSTR + 32u * kk + b_lane;
                    LDSM4(bVh[0][0], bVh[0][1], bVh[1][0], bVh[1][1], br);
                    LDSM4(bVl[0][0], bVl[0][1], bVl[1][0], bVl[1][1], br + FK_BYTES);
                    #pragma unroll
                    for (int jj = 0; jj < 2; jj++) {
                        const int j = p * 2 + jj;
                        MMA16816(o[j], aPh, bVh[jj]);
                        MMA16816(o[j], aPl, bVh[jj]);
                        MMA16816(o[j], aPh, bVl[jj]);
                    }
                }
            }
        }
        __syncthreads();
    }

    #pragma unroll
    for (int u = 0; u < 2; u++) {
        float inv = 1.0f / l_i[u];
        int row = b * Tn + qb * 128 + w * 16 + u * 8 + g;
        #pragma unroll
        for (int j = 0; j < 8; j++) {
            float p0 = o[j][2 * u] * inv;
            float p1 = o[j][2 * u + 1] * inv;
            __nv_bfloat16 h0 = __float2bfloat16(p0);
            __nv_bfloat16 h1 = __float2bfloat16(p1);
            uint32_t hi = ((uint32_t)*(uint16_t*)&h1 << 16) | *(uint16_t*)&h0;
            uint32_t lo = pack_bf2(p0 - __bfloat162float(h0),
                                   p1 - __bfloat162float(h1));
            size_t off = (size_t)row * Cn + h * HDn + j * 8 + 2 * t;
            *(uint32_t*)(ah + off) = hi;
            *(uint32_t*)(al + off) = lo;
        }
    }
}

// ---------------------------------------------------------------------------
extern "C" void kernel_launch(void* const* d_in, const int* in_sizes, int n_in,
                              void* d_out, int out_size)
{
    const float* x     = (const float*)d_in[0];
    const float* fcos  = (const float*)d_in[1];
    const float* fsin  = (const float*)d_in[2];
    const float* Wqkv  = (const float*)d_in[3];
    const float* bqkv  = (const float*)d_in[4];
    const float* Wproj = (const float*)d_in[5];
    const float* bproj = (const float*)d_in[6];
    float* out = (float*)d_out;

    unsigned char* pool = nullptr;
    cudaGetSymbolAddress((void**)&pool, g_pool);
    float* qkv = (float*)(pool + OFF_QKV);
    __nv_bfloat16* xh  = (__nv_bfloat16*)(pool + OFF_XH);
    __nv_bfloat16* xl  = (__nv_bfloat16*)(pool + OFF_XL);
    __nv_bfloat16* wqh = (__nv_bfloat16*)(pool + OFF_WQH);
    __nv_bfloat16* wql = (__nv_bfloat16*)(pool + OFF_WQL);
    __nv_bfloat16* wph = (__nv_bfloat16*)(pool + OFF_WPH);
    __nv_bfloat16* wpl = (__nv_bfloat16*)(pool + OFF_WPL);
    __nv_bfloat16* ah  = (__nv_bfloat16*)(pool + OFF_AH);
    __nv_bfloat16* al  = (__nv_bfloat16*)(pool + OFF_AL);
    __nv_bfloat16* qh  = (__nv_bfloat16*)(pool + OFF_QH);
    __nv_bfloat16* ql  = (__nv_bfloat16*)(pool + OFF_QL);
    __nv_bfloat16* kh  = (__nv_bfloat16*)(pool + OFF_KH);
    __nv_bfloat16* kl  = (__nv_bfloat16*)(pool + OFF_KL);
    __nv_bfloat16* vh  = (__nv_bfloat16*)(pool + OFF_VH);
    __nv_bfloat16* vl  = (__nv_bfloat16*)(pool + OFF_VL);

    cudaFuncSetAttribute(gemm_bf16x3_kernel,
                         cudaFuncAttributeMaxDynamicSharedMemorySize, GEMM_SMEM);
    cudaFuncSetAttribute(gemm_bf16x3_kernel,
                         cudaFuncAttributePreferredSharedMemoryCarveout, 100);
    cudaFuncSetAttribute(flash_mma_kernel,
                         cudaFuncAttributeMaxDynamicSharedMemorySize, FA2_SMEM);
    cudaFuncSetAttribute(flash_mma_kernel,
                         cudaFuncAttributePreferredSharedMemoryCarveout, 100);

    // prep
    split_kernel<<<(Mn * Cn) / 256, 256>>>(x, xh, xl, Mn * Cn);
    transpose_split_kernel<<<dim3(N3n / 32, Kn / 32), 256>>>(Wqkv, wqh, wql, Kn, N3n);
    transpose_split_kernel<<<dim3(Cn / 32, Kn / 32), 256>>>(Wproj, wph, wpl, Kn, Cn);

    // 1) qkv = x @ Wqkv + bqkv
    gemm_bf16x3_kernel<<<dim3(N3n / 128, Mn / 128), 256, GEMM_SMEM>>>(
        N3n, xh, xl, wqh, wql, bqkv, qkv);

    // 2) RoPE + split Q,K ; split+transpose V
    rope_split_qk_kernel<<<(Bn * Tn * Hn * 32) / 256, 256>>>(
        qkv, fcos, fsin, qh, ql, kh, kl);
    v_split_t_kernel<<<dim3(Tn / 64, Hn, Bn), 256>>>(qkv, vh, vl);

    // 3) flash attention (mma) -> ah/al bf16 hi/lo
    flash_mma_kernel<<<dim3(Tn / 128, Hn, Bn), 256, FA2_SMEM>>>(
        qh, ql, kh, kl, vh, vl, ah, al);

    // 4) out = att @ Wproj + bproj
    gemm_bf16x3_kernel<<<dim3(Cn / 128, Mn / 128), 256, GEMM_SMEM>>>(
        Cn, ah, al, wph, wpl, bproj, out);
}